// round 2
// baseline (speedup 1.0000x reference)
#include <cuda_runtime.h>
#include <math.h>

#define BB 8
#define NN 4096
#define CC 512
#define HH 8
#define DH 64
#define EPSF 1e-12f

// Scratch (allocation-free rule: __device__ globals)
__device__ float g_kv[33554432];      // [B,N,1024] = 128MB : k at [0,512), v at [512,1024)
__device__ float g_q [16777216];      // [B,N,512]  = 64MB
__device__ float g_nk_part[16 * BB * CC];
__device__ float g_nq_part[16 * BB * CC];
__device__ float g_Spart[8 * BB * HH * DH * DH];   // 8 N-splits of raw Gram
__device__ float g_attn [BB * HH * DH * DH];
__device__ float g_Wc[2097152];       // [B,512,512] = 8MB folded weights

// ---------------------------------------------------------------------------
// Generic SGEMM:  C[m,n] = sum_k A[m,k] * W[n,k]  (+ bias[n]),  batched by z
// BM=BN=128, BK=16, 256 threads, 8x8 microtile. All dims divide tiles exactly.
// ---------------------------------------------------------------------------
__global__ __launch_bounds__(256) void sgemm_tn(
    const float* __restrict__ A, int lda, long long sA,
    const float* __restrict__ W, int ldw, long long sW,
    float* __restrict__ Cout, int ldc, long long sC,
    const float* __restrict__ bias, int K)
{
    const int bz = blockIdx.z;
    A    += (long long)bz * sA;
    W    += (long long)bz * sW;
    Cout += (long long)bz * sC;

    const int m0 = blockIdx.y * 128;
    const int n0 = blockIdx.x * 128;

    __shared__ float As[16][128];
    __shared__ float Ws[16][128];

    const int t    = threadIdx.x;
    const int lrow = t >> 2;          // 0..63
    const int lcol = (t & 3) * 4;     // k offset 0,4,8,12
    const int tx   = t & 15;          // 16 col groups
    const int ty   = t >> 4;          // 16 row groups

    float acc[8][8];
    #pragma unroll
    for (int i = 0; i < 8; ++i)
        #pragma unroll
        for (int j = 0; j < 8; ++j) acc[i][j] = 0.0f;

    for (int k0 = 0; k0 < K; k0 += 16) {
        float4 a0 = *(const float4*)(A + (long long)(m0 + lrow     ) * lda + k0 + lcol);
        float4 a1 = *(const float4*)(A + (long long)(m0 + lrow + 64) * lda + k0 + lcol);
        float4 w0 = *(const float4*)(W + (long long)(n0 + lrow     ) * ldw + k0 + lcol);
        float4 w1 = *(const float4*)(W + (long long)(n0 + lrow + 64) * ldw + k0 + lcol);

        __syncthreads();
        As[lcol+0][lrow]      = a0.x; As[lcol+1][lrow]      = a0.y;
        As[lcol+2][lrow]      = a0.z; As[lcol+3][lrow]      = a0.w;
        As[lcol+0][lrow+64]   = a1.x; As[lcol+1][lrow+64]   = a1.y;
        As[lcol+2][lrow+64]   = a1.z; As[lcol+3][lrow+64]   = a1.w;
        Ws[lcol+0][lrow]      = w0.x; Ws[lcol+1][lrow]      = w0.y;
        Ws[lcol+2][lrow]      = w0.z; Ws[lcol+3][lrow]      = w0.w;
        Ws[lcol+0][lrow+64]   = w1.x; Ws[lcol+1][lrow+64]   = w1.y;
        Ws[lcol+2][lrow+64]   = w1.z; Ws[lcol+3][lrow+64]   = w1.w;
        __syncthreads();

        #pragma unroll
        for (int k = 0; k < 16; ++k) {
            float a[8], w[8];
            *(float4*)(a    ) = *(float4*)&As[k][ty * 8];
            *(float4*)(a + 4) = *(float4*)&As[k][ty * 8 + 4];
            *(float4*)(w    ) = *(float4*)&Ws[k][tx * 8];
            *(float4*)(w + 4) = *(float4*)&Ws[k][tx * 8 + 4];
            #pragma unroll
            for (int i = 0; i < 8; ++i)
                #pragma unroll
                for (int j = 0; j < 8; ++j)
                    acc[i][j] += a[i] * w[j];
        }
    }

    #pragma unroll
    for (int i = 0; i < 8; ++i) {
        const int m = m0 + ty * 8 + i;
        float* crow = Cout + (long long)m * ldc + n0 + tx * 8;
        if (bias) {
            const float* bp = bias + n0 + tx * 8;
            #pragma unroll
            for (int j = 0; j < 8; ++j) acc[i][j] += bp[j];
        }
        *(float4*)(crow    ) = *(float4*)&acc[i][0];
        *(float4*)(crow + 4) = *(float4*)&acc[i][4];
    }
}

// ---------------------------------------------------------------------------
// Partial column sum-of-squares for k (first 512 of kv) and q, over n chunks.
// grid (16 chunks, B), 256 threads; deterministic (no atomics).
// ---------------------------------------------------------------------------
__global__ __launch_bounds__(256) void sumsq_kernel(
    const float* __restrict__ kv, const float* __restrict__ q,
    float* __restrict__ nk_part, float* __restrict__ nq_part)
{
    const int chunk = blockIdx.x;
    const int b     = blockIdx.y;
    const int t     = threadIdx.x;
    const int n0    = chunk * 256;

    const float* kvb = kv + ((long long)b * NN + n0) * 1024;
    const float* qb  = q  + ((long long)b * NN + n0) * 512;

    float ak0 = 0.f, ak1 = 0.f, aq0 = 0.f, aq1 = 0.f;
    for (int n = 0; n < 256; ++n) {
        float v0 = kvb[(long long)n * 1024 + t];        ak0 += v0 * v0;
        float v1 = kvb[(long long)n * 1024 + t + 256];  ak1 += v1 * v1;
        float w0 = qb [(long long)n * 512  + t];        aq0 += w0 * w0;
        float w1 = qb [(long long)n * 512  + t + 256];  aq1 += w1 * w1;
    }
    nk_part[(chunk * BB + b) * CC + t]       = ak0;
    nk_part[(chunk * BB + b) * CC + t + 256] = ak1;
    nq_part[(chunk * BB + b) * CC + t]       = aq0;
    nq_part[(chunk * BB + b) * CC + t + 256] = aq1;
}

// ---------------------------------------------------------------------------
// Raw Gram partials: Spart[ns,b,h,d,e] = sum_{n in split ns} q[d,n]*k[e,n]
// grid (8 splits, H, B), 256 threads, 4x4 microtile of the 64x64 output.
// ---------------------------------------------------------------------------
__global__ __launch_bounds__(256) void gram_kernel(
    const float* __restrict__ q, const float* __restrict__ kv,
    float* __restrict__ Spart)
{
    const int ns = blockIdx.x, h = blockIdx.y, b = blockIdx.z;
    const int n0 = ns * (NN / 8);

    __shared__ float qs[16][64];
    __shared__ float ks[16][64];

    const int t  = threadIdx.x;
    const int lr = t >> 4;          // 0..15 row within n-tile
    const int lc = (t & 15) * 4;    // 0..60 col
    const int tx = t & 15, ty = t >> 4;

    const float* qbase = q  + ((long long)b * NN) * 512  + h * 64;
    const float* kbase = kv + ((long long)b * NN) * 1024 + h * 64;

    float acc[4][4];
    #pragma unroll
    for (int i = 0; i < 4; ++i)
        #pragma unroll
        for (int j = 0; j < 4; ++j) acc[i][j] = 0.0f;

    for (int nt = 0; nt < NN / 8; nt += 16) {
        const int n = n0 + nt;
        float4 qv = *(const float4*)(qbase + (long long)(n + lr) * 512  + lc);
        float4 kvv= *(const float4*)(kbase + (long long)(n + lr) * 1024 + lc);
        __syncthreads();
        *(float4*)&qs[lr][lc] = qv;
        *(float4*)&ks[lr][lc] = kvv;
        __syncthreads();
        #pragma unroll
        for (int kk = 0; kk < 16; ++kk) {
            float a[4], c[4];
            *(float4*)a = *(float4*)&qs[kk][ty * 4];
            *(float4*)c = *(float4*)&ks[kk][tx * 4];
            #pragma unroll
            for (int i = 0; i < 4; ++i)
                #pragma unroll
                for (int j = 0; j < 4; ++j)
                    acc[i][j] += a[i] * c[j];
        }
    }

    float* dst = Spart + ((((long long)ns * BB + b) * HH + h) * DH) * DH;
    #pragma unroll
    for (int i = 0; i < 4; ++i)
        #pragma unroll
        for (int j = 0; j < 4; ++j)
            dst[(ty * 4 + i) * 64 + tx * 4 + j] = acc[i][j];
}

// ---------------------------------------------------------------------------
// Reduce partials, L2-norm divide, temperature, softmax over e. grid (H,B), 64 thr.
// ---------------------------------------------------------------------------
__global__ void attn_kernel(
    const float* __restrict__ Spart,
    const float* __restrict__ nq_part, const float* __restrict__ nk_part,
    const float* __restrict__ temp, float* __restrict__ attn)
{
    const int h = blockIdx.x, b = blockIdx.y;
    const int d = threadIdx.x;
    __shared__ float snk[64];

    const int c = h * 64 + d;
    float sk = 0.f, sq = 0.f;
    #pragma unroll
    for (int ch = 0; ch < 16; ++ch) {
        sk += nk_part[(ch * BB + b) * CC + c];
        sq += nq_part[(ch * BB + b) * CC + c];
    }
    snk[d] = fmaxf(sqrtf(sk), EPSF);
    const float nqv = fmaxf(sqrtf(sq), EPSF);
    __syncthreads();

    const float tv = temp[h];
    float vals[64];
    float mx = -1e30f;
    #pragma unroll
    for (int e = 0; e < 64; ++e) {
        float s = 0.f;
        #pragma unroll
        for (int ns = 0; ns < 8; ++ns)
            s += Spart[((((long long)ns * BB + b) * HH + h) * DH + d) * DH + e];
        float v = s * tv / (nqv * snk[e]);
        vals[e] = v;
        mx = fmaxf(mx, v);
    }
    float sum = 0.f;
    #pragma unroll
    for (int e = 0; e < 64; ++e) { vals[e] = expf(vals[e] - mx); sum += vals[e]; }
    const float inv = 1.0f / sum;
    float* row = attn + (((long long)(b * HH + h) * DH + d) * DH);
    #pragma unroll
    for (int e = 0; e < 64; ++e) row[e] = vals[e] * inv;
}

// ---------------------------------------------------------------------------
// Fold attn into projection: Wc[b, o, h*64+e] = sum_d proj_w[o, h*64+d]*attn[b,h,d,e]
// grid (4 o-splits, H, B), 256 threads.
// ---------------------------------------------------------------------------
__global__ __launch_bounds__(256) void fold_kernel(
    const float* __restrict__ attn, const float* __restrict__ projw,
    float* __restrict__ Wc)
{
    const int oz = blockIdx.x, h = blockIdx.y, b = blockIdx.z;
    __shared__ float at[64][64];

    const int t = threadIdx.x;
    const float* Abh = attn + (((long long)(b * HH + h) * DH) * DH);
    for (int i = t; i < 4096; i += 256) at[i >> 6][i & 63] = Abh[i];
    __syncthreads();

    const int e  = t & 63;
    const int og = t >> 6;              // 0..3
    const int obase = oz * 128 + og * 32;

    for (int oi = 0; oi < 32; ++oi) {
        const int o = obase + oi;
        const float4* pr = (const float4*)(projw + (long long)o * CC + h * 64);
        float acc = 0.f;
        #pragma unroll
        for (int d4 = 0; d4 < 16; ++d4) {
            float4 p = pr[d4];
            acc += p.x * at[d4 * 4 + 0][e];
            acc += p.y * at[d4 * 4 + 1][e];
            acc += p.z * at[d4 * 4 + 2][e];
            acc += p.w * at[d4 * 4 + 3][e];
        }
        Wc[((long long)b * CC + o) * CC + h * 64 + e] = acc;
    }
}

// ---------------------------------------------------------------------------
extern "C" void kernel_launch(void* const* d_in, const int* in_sizes, int n_in,
                              void* d_out, int out_size)
{
    (void)in_sizes; (void)n_in; (void)out_size;
    const float* x      = (const float*)d_in[0];   // [8,4096,512]
    const float* y      = (const float*)d_in[1];   // [8,4096,256]
    const float* kv_w   = (const float*)d_in[2];   // [1024,512]
    const float* q_w    = (const float*)d_in[3];   // [512,256]
    const float* proj_w = (const float*)d_in[4];   // [512,512]
    const float* proj_b = (const float*)d_in[5];   // [512]
    const float* temp   = (const float*)d_in[6];   // [8]
    float* out = (float*)d_out;

    float *kvp, *qp, *nkp, *nqp, *Sp, *ap, *Wcp;
    cudaGetSymbolAddress((void**)&kvp, g_kv);
    cudaGetSymbolAddress((void**)&qp,  g_q);
    cudaGetSymbolAddress((void**)&nkp, g_nk_part);
    cudaGetSymbolAddress((void**)&nqp, g_nq_part);
    cudaGetSymbolAddress((void**)&Sp,  g_Spart);
    cudaGetSymbolAddress((void**)&ap,  g_attn);
    cudaGetSymbolAddress((void**)&Wcp, g_Wc);

    // 1) kv = x @ kv_w^T : M=32768, N=1024, K=512
    sgemm_tn<<<dim3(1024 / 128, 32768 / 128, 1), 256>>>(
        x, 512, 0, kv_w, 512, 0, kvp, 1024, 0, nullptr, 512);

    // 2) q = y @ q_w^T : M=32768, N=512, K=256
    sgemm_tn<<<dim3(512 / 128, 32768 / 128, 1), 256>>>(
        y, 256, 0, q_w, 256, 0, qp, 512, 0, nullptr, 256);

    // 3) column sum-of-squares partials
    sumsq_kernel<<<dim3(16, BB), 256>>>(kvp, qp, nkp, nqp);

    // 4) raw Gram partials
    gram_kernel<<<dim3(8, HH, BB), 256>>>(qp, kvp, Sp);

    // 5) normalize + temperature + softmax
    attn_kernel<<<dim3(HH, BB), 64>>>(Sp, nqp, nkp, temp, ap);

    // 6) fold attn into projection weights
    fold_kernel<<<dim3(4, HH, BB), 256>>>(ap, proj_w, Wcp);

    // 7) out[b] = V_b @ Wc_b^T + proj_b : batched M=4096, N=512, K=512
    sgemm_tn<<<dim3(512 / 128, 4096 / 128, BB), 256>>>(
        kvp + 512, 1024, (long long)NN * 1024,
        Wcp, 512, (long long)CC * CC,
        out, 512, (long long)NN * CC,
        proj_b, 512);
}

// round 6
// speedup vs baseline: 1.4416x; 1.4416x over previous
#include <cuda_runtime.h>
#include <cuda_bf16.h>
#include <mma.h>
#include <math.h>
#include <stdint.h>

using namespace nvcuda;

#define BB 8
#define NN 4096
#define CC 512
#define HH 8
#define DH 64
#define EPSF 1e-12f

// smem tile geometry: 128 rows x 32 bf16, padded to 40 elems (80B) per row
#define SPITCH 40
#define PLANE  5120          // 128*40 bf16 elems per plane
#define STAGE_E 20480        // 4 planes (Ahi, Alo, Bhi, Blo)
#define NST 3
#define SMEM_DYN 122880      // 3 stages * 20480 elems * 2B (>= epilogue 128*132*4)

// ---------------- scratch (device globals; no allocs) ----------------
__device__ __nv_bfloat16 g_xh [16777216], g_xl [16777216];   // x planes  [B*N,512]
__device__ __nv_bfloat16 g_yh [ 8388608], g_yl [ 8388608];   // y planes  [B*N,256]
__device__ __nv_bfloat16 g_wh [  524288], g_wl [  524288];   // kv_w      [1024,512]
__device__ __nv_bfloat16 g_qwh[  131072], g_qwl[  131072];   // q_w       [512,256]
__device__ __nv_bfloat16 g_kvh[33554432], g_kvl[33554432];   // kv        [B*N,1024]
__device__ __nv_bfloat16 g_qh [16777216], g_ql [16777216];   // q         [B*N,512]
__device__ __nv_bfloat16 g_Wch[ 2097152], g_Wcl[ 2097152];   // Wc        [B,512,512]
__device__ float g_nk_part[16 * BB * CC];
__device__ float g_nq_part[16 * BB * CC];
__device__ float g_Spart[8 * BB * HH * DH * DH];
__device__ float g_attn [BB * HH * DH * DH];

// ---------------- helpers ----------------
__device__ __forceinline__ uint32_t smem_u32(const void* p) {
    uint32_t a;
    asm("{ .reg .u64 t; cvta.to.shared.u64 t, %1; cvt.u32.u64 %0, t; }" : "=r"(a) : "l"(p));
    return a;
}
__device__ __forceinline__ void split2(float v, __nv_bfloat16& h, __nv_bfloat16& l) {
    h = __float2bfloat16(v);
    l = __float2bfloat16(v - __bfloat162float(h));
}
__device__ __forceinline__ uint32_t pack2(__nv_bfloat16 a, __nv_bfloat16 b) {
    return (uint32_t)__bfloat16_as_ushort(a) | ((uint32_t)__bfloat16_as_ushort(b) << 16);
}
__device__ __forceinline__ float bsum(__nv_bfloat16 h, __nv_bfloat16 l) {
    return __bfloat162float(h) + __bfloat162float(l);
}
#define CPA16(s, g)  asm volatile("cp.async.cg.shared.global [%0], [%1], 16;" :: "r"(s), "l"(g))
#define CPA_COMMIT() asm volatile("cp.async.commit_group;")
#define CPA_WAIT1()  asm volatile("cp.async.wait_group 1;")
#define CPA_WAIT0()  asm volatile("cp.async.wait_group 0;")

// ---------------- conversion: fp32 -> hi/lo bf16 planes ----------------
__global__ void conv_kernel(const float4* __restrict__ in,
                            uint2* __restrict__ oh, uint2* __restrict__ ol, int n4) {
    int i = blockIdx.x * 256 + threadIdx.x;
    if (i < n4) {
        float4 v = in[i];
        __nv_bfloat16 h0, h1, h2, h3, l0, l1, l2, l3;
        split2(v.x, h0, l0); split2(v.y, h1, l1);
        split2(v.z, h2, l2); split2(v.w, h3, l3);
        oh[i] = make_uint2(pack2(h0, h1), pack2(h2, h3));
        ol[i] = make_uint2(pack2(l0, l1), pack2(l2, l3));
    }
}

// ---------------- wmma split GEMM ----------------
// C[m,n] = sum_k A[m,k]*B[n,k], A = Ah+Al, B = Bh+Bl (bf16 planes).
// Accumulates Ah*Bh + Ah*Bl + Al*Bh in fp32 (Markidis split).
// mode 0: write hi/lo bf16 planes Ch, Cl. mode 2: write f32 Cf + bias.
__global__ __launch_bounds__(256, 1)
void gemm_wm(const __nv_bfloat16* __restrict__ Ah, const __nv_bfloat16* __restrict__ Al,
             int pA, long long sA,
             const __nv_bfloat16* __restrict__ Bh, const __nv_bfloat16* __restrict__ Bl,
             int pB, long long sB,
             __nv_bfloat16* __restrict__ Ch, __nv_bfloat16* __restrict__ Cl,
             float* __restrict__ Cf, int pC, long long sC,
             const float* __restrict__ bias, int K, int mode)
{
    extern __shared__ char smraw[];
    __nv_bfloat16* sbf = (__nv_bfloat16*)smraw;
    float* sf = (float*)smraw;
    const int t = threadIdx.x;
    const int wid = t >> 5;
    const int bz = blockIdx.z;
    Ah += (long long)bz * sA; Al += (long long)bz * sA;
    Bh += (long long)bz * sB; Bl += (long long)bz * sB;
    const int m0 = blockIdx.y * 128, n0 = blockIdx.x * 128;
    const int wm = (wid & 1) * 64, wn = (wid >> 1) * 32;   // warp tile 64x32

    const int prow = t >> 2;        // 0..63
    const int pch  = (t & 3) * 8;   // k-elem offset (8 elems = 16B)

    const __nv_bfloat16* gp[4] = { Ah + (long long)m0 * pA, Al + (long long)m0 * pA,
                                   Bh + (long long)n0 * pB, Bl + (long long)n0 * pB };
    const int pp[4] = { pA, pA, pB, pB };

    const int nkb = K >> 5;

    auto produce = [&](int s, int kb) {
        const uint32_t sb = smem_u32(sbf + s * STAGE_E);
        #pragma unroll
        for (int pl = 0; pl < 4; ++pl) {
            #pragma unroll
            for (int hf = 0; hf < 2; ++hf) {
                const int row = hf * 64 + prow;
                const __nv_bfloat16* g = gp[pl] + (long long)row * pp[pl] + kb + pch;
                const uint32_t sa = sb + (uint32_t)(pl * PLANE + row * SPITCH + pch) * 2u;
                CPA16(sa, g);
            }
        }
        CPA_COMMIT();
    };

    produce(0, 0);
    produce(1, 32);

    wmma::fragment<wmma::accumulator, 16, 16, 16, float> acc[4][2];
    #pragma unroll
    for (int i = 0; i < 4; ++i)
        #pragma unroll
        for (int j = 0; j < 2; ++j) wmma::fill_fragment(acc[i][j], 0.0f);

    for (int i = 0; i < nkb; ++i) {
        if (i + 1 < nkb) { CPA_WAIT1(); } else { CPA_WAIT0(); }
        __syncthreads();
        const int s = i % NST;
        const __nv_bfloat16* sa_h = sbf + s * STAGE_E;
        const __nv_bfloat16* sa_l = sa_h + PLANE;
        const __nv_bfloat16* sb_h = sa_h + 2 * PLANE;
        const __nv_bfloat16* sb_l = sa_h + 3 * PLANE;
        #pragma unroll
        for (int kk = 0; kk < 32; kk += 16) {
            wmma::fragment<wmma::matrix_a, 16, 16, 16, __nv_bfloat16, wmma::row_major> fah[4], fal[4];
            wmma::fragment<wmma::matrix_b, 16, 16, 16, __nv_bfloat16, wmma::col_major> fbh[2], fbl[2];
            #pragma unroll
            for (int im = 0; im < 4; ++im) {
                wmma::load_matrix_sync(fah[im], sa_h + (wm + im * 16) * SPITCH + kk, SPITCH);
                wmma::load_matrix_sync(fal[im], sa_l + (wm + im * 16) * SPITCH + kk, SPITCH);
            }
            #pragma unroll
            for (int in_ = 0; in_ < 2; ++in_) {
                wmma::load_matrix_sync(fbh[in_], sb_h + (wn + in_ * 16) * SPITCH + kk, SPITCH);
                wmma::load_matrix_sync(fbl[in_], sb_l + (wn + in_ * 16) * SPITCH + kk, SPITCH);
            }
            #pragma unroll
            for (int im = 0; im < 4; ++im)
                #pragma unroll
                for (int in_ = 0; in_ < 2; ++in_) {
                    wmma::mma_sync(acc[im][in_], fah[im], fbh[in_], acc[im][in_]);
                    wmma::mma_sync(acc[im][in_], fah[im], fbl[in_], acc[im][in_]);
                    wmma::mma_sync(acc[im][in_], fal[im], fbh[in_], acc[im][in_]);
                }
        }
        __syncthreads();
        if (i + 2 < nkb) produce((i + 2) % NST, (i + 2) * 32);
    }

    // ---- epilogue: stage fp32 tile in smem (pitch 132, reuses pipeline smem) ----
    __syncthreads();
    #pragma unroll
    for (int im = 0; im < 4; ++im)
        #pragma unroll
        for (int in_ = 0; in_ < 2; ++in_)
            wmma::store_matrix_sync(sf + (wm + im * 16) * 132 + wn + in_ * 16,
                                    acc[im][in_], 132, wmma::mem_row_major);
    __syncthreads();

    const int row = t >> 1, half = (t & 1) * 64;
    const float* sr = sf + row * 132 + half;
    if (mode == 0) {
        __nv_bfloat16* dh = Ch + (long long)bz * sC + (long long)(m0 + row) * pC + n0 + half;
        __nv_bfloat16* dl = Cl + (long long)bz * sC + (long long)(m0 + row) * pC + n0 + half;
        #pragma unroll
        for (int j = 0; j < 8; ++j) {
            uint4 hv, lv;
            uint32_t* hp = (uint32_t*)&hv;
            uint32_t* lp = (uint32_t*)&lv;
            #pragma unroll
            for (int e = 0; e < 4; ++e) {
                __nv_bfloat16 h0, h1, l0, l1;
                split2(sr[j * 8 + e * 2 + 0], h0, l0);
                split2(sr[j * 8 + e * 2 + 1], h1, l1);
                hp[e] = pack2(h0, h1);
                lp[e] = pack2(l0, l1);
            }
            *(uint4*)(dh + j * 8) = hv;
            *(uint4*)(dl + j * 8) = lv;
        }
    } else {
        float* dst = Cf + (long long)bz * sC + (long long)(m0 + row) * pC + n0 + half;
        const float* bp = bias + n0 + half;
        #pragma unroll
        for (int j = 0; j < 16; ++j) {
            float4 v = make_float4(sr[j * 4 + 0] + bp[j * 4 + 0],
                                   sr[j * 4 + 1] + bp[j * 4 + 1],
                                   sr[j * 4 + 2] + bp[j * 4 + 2],
                                   sr[j * 4 + 3] + bp[j * 4 + 3]);
            *(float4*)(dst + j * 4) = v;
        }
    }
}

// ---------------- sumsq (plane inputs) ----------------
__global__ __launch_bounds__(256) void sumsq_kernel(
    const __nv_bfloat16* __restrict__ kvh, const __nv_bfloat16* __restrict__ kvl,
    const __nv_bfloat16* __restrict__ qh,  const __nv_bfloat16* __restrict__ ql,
    float* __restrict__ nk_part, float* __restrict__ nq_part)
{
    const int chunk = blockIdx.x, b = blockIdx.y, t = threadIdx.x;
    const int n0 = chunk * 256;
    const long long kb = ((long long)b * NN + n0) * 1024;
    const long long qb = ((long long)b * NN + n0) * 512;
    float ak0 = 0.f, ak1 = 0.f, aq0 = 0.f, aq1 = 0.f;
    for (int n = 0; n < 256; ++n) {
        float v0 = bsum(kvh[kb + (long long)n * 1024 + t],       kvl[kb + (long long)n * 1024 + t]);
        float v1 = bsum(kvh[kb + (long long)n * 1024 + t + 256], kvl[kb + (long long)n * 1024 + t + 256]);
        float w0 = bsum(qh [qb + (long long)n * 512  + t],       ql [qb + (long long)n * 512  + t]);
        float w1 = bsum(qh [qb + (long long)n * 512  + t + 256], ql [qb + (long long)n * 512  + t + 256]);
        ak0 += v0 * v0; ak1 += v1 * v1; aq0 += w0 * w0; aq1 += w1 * w1;
    }
    nk_part[(chunk * BB + b) * CC + t]       = ak0;
    nk_part[(chunk * BB + b) * CC + t + 256] = ak1;
    nq_part[(chunk * BB + b) * CC + t]       = aq0;
    nq_part[(chunk * BB + b) * CC + t + 256] = aq1;
}

// ---------------- gram (plane inputs) ----------------
__global__ __launch_bounds__(256) void gram_kernel(
    const __nv_bfloat16* __restrict__ qh, const __nv_bfloat16* __restrict__ ql,
    const __nv_bfloat16* __restrict__ kvh, const __nv_bfloat16* __restrict__ kvl,
    float* __restrict__ Spart)
{
    const int ns = blockIdx.x, h = blockIdx.y, b = blockIdx.z;
    const int n0 = ns * (NN / 8);
    __shared__ float qs[16][64];
    __shared__ float ks[16][64];
    const int t = threadIdx.x;
    const int lr = t >> 4;
    const int lc = (t & 15) * 4;
    const int tx = t & 15, ty = t >> 4;
    const long long qbase = ((long long)b * NN) * 512 + h * 64;
    const long long kbase = ((long long)b * NN) * 1024 + h * 64;

    float acc[4][4];
    #pragma unroll
    for (int i = 0; i < 4; ++i)
        #pragma unroll
        for (int j = 0; j < 4; ++j) acc[i][j] = 0.0f;

    for (int nt = 0; nt < NN / 8; nt += 16) {
        const int n = n0 + nt;
        const long long qo = qbase + (long long)(n + lr) * 512 + lc;
        const long long ko = kbase + (long long)(n + lr) * 1024 + lc;
        float2 qa0 = __bfloat1622float2(*(const __nv_bfloat162*)(qh + qo));
        float2 qa1 = __bfloat1622float2(*(const __nv_bfloat162*)(qh + qo + 2));
        float2 qb0 = __bfloat1622float2(*(const __nv_bfloat162*)(ql + qo));
        float2 qb1 = __bfloat1622float2(*(const __nv_bfloat162*)(ql + qo + 2));
        float2 ka0 = __bfloat1622float2(*(const __nv_bfloat162*)(kvh + ko));
        float2 ka1 = __bfloat1622float2(*(const __nv_bfloat162*)(kvh + ko + 2));
        float2 kb0 = __bfloat1622float2(*(const __nv_bfloat162*)(kvl + ko));
        float2 kb1 = __bfloat1622float2(*(const __nv_bfloat162*)(kvl + ko + 2));
        __syncthreads();
        qs[lr][lc + 0] = qa0.x + qb0.x; qs[lr][lc + 1] = qa0.y + qb0.y;
        qs[lr][lc + 2] = qa1.x + qb1.x; qs[lr][lc + 3] = qa1.y + qb1.y;
        ks[lr][lc + 0] = ka0.x + kb0.x; ks[lr][lc + 1] = ka0.y + kb0.y;
        ks[lr][lc + 2] = ka1.x + kb1.x; ks[lr][lc + 3] = ka1.y + kb1.y;
        __syncthreads();
        #pragma unroll
        for (int kk = 0; kk < 16; ++kk) {
            float a[4], c[4];
            *(float4*)a = *(float4*)&qs[kk][ty * 4];
            *(float4*)c = *(float4*)&ks[kk][tx * 4];
            #pragma unroll
            for (int i = 0; i < 4; ++i)
                #pragma unroll
                for (int j = 0; j < 4; ++j)
                    acc[i][j] += a[i] * c[j];
        }
    }
    float* dst = g_Spart + ((((long long)ns * BB + b) * HH + h) * DH) * DH;
    (void)Spart;
    #pragma unroll
    for (int i = 0; i < 4; ++i)
        #pragma unroll
        for (int j = 0; j < 4; ++j)
            dst[(ty * 4 + i) * 64 + tx * 4 + j] = acc[i][j];
}

// ---------------- attn: reduce + normalize + softmax ----------------
__global__ void attn_kernel(
    const float* __restrict__ Spart,
    const float* __restrict__ nq_part, const float* __restrict__ nk_part,
    const float* __restrict__ temp, float* __restrict__ attn)
{
    const int h = blockIdx.x, b = blockIdx.y, d = threadIdx.x;
    __shared__ float snk[64];
    const int c = h * 64 + d;
    float sk = 0.f, sq = 0.f;
    #pragma unroll
    for (int ch = 0; ch < 16; ++ch) {
        sk += nk_part[(ch * BB + b) * CC + c];
        sq += nq_part[(ch * BB + b) * CC + c];
    }
    snk[d] = fmaxf(sqrtf(sk), EPSF);
    const float nqv = fmaxf(sqrtf(sq), EPSF);
    __syncthreads();
    const float tv = temp[h];
    float vals[64];
    float mx = -1e30f;
    #pragma unroll
    for (int e = 0; e < 64; ++e) {
        float s = 0.f;
        #pragma unroll
        for (int ns = 0; ns < 8; ++ns)
            s += Spart[((((long long)ns * BB + b) * HH + h) * DH + d) * DH + e];
        float v = s * tv / (nqv * snk[e]);
        vals[e] = v;
        mx = fmaxf(mx, v);
    }
    float sum = 0.f;
    #pragma unroll
    for (int e = 0; e < 64; ++e) { vals[e] = expf(vals[e] - mx); sum += vals[e]; }
    const float inv = 1.0f / sum;
    float* row = attn + (((long long)(b * HH + h) * DH) * DH) + (long long)d * DH;
    #pragma unroll
    for (int e = 0; e < 64; ++e) row[e] = vals[e] * inv;
}

// ---------------- fold attn into proj (writes Wc hi/lo planes) ----------------
__global__ __launch_bounds__(256) void fold_kernel(
    const float* __restrict__ attn, const float* __restrict__ projw,
    __nv_bfloat16* __restrict__ Wch, __nv_bfloat16* __restrict__ Wcl)
{
    const int oz = blockIdx.x, h = blockIdx.y, b = blockIdx.z;
    __shared__ float at[64][64];
    const int t = threadIdx.x;
    const float* Abh = attn + (((long long)(b * HH + h) * DH) * DH);
    for (int i = t; i < 4096; i += 256) at[i >> 6][i & 63] = Abh[i];
    __syncthreads();
    const int e = t & 63;
    const int og = t >> 6;
    const int obase = oz * 128 + og * 32;
    for (int oi = 0; oi < 32; ++oi) {
        const int o = obase + oi;
        const float4* pr = (const float4*)(projw + (long long)o * CC + h * 64);
        float acc = 0.f;
        #pragma unroll
        for (int d4 = 0; d4 < 16; ++d4) {
            float4 p = pr[d4];
            acc += p.x * at[d4 * 4 + 0][e];
            acc += p.y * at[d4 * 4 + 1][e];
            acc += p.z * at[d4 * 4 + 2][e];
            acc += p.w * at[d4 * 4 + 3][e];
        }
        __nv_bfloat16 hh, ll;
        split2(acc, hh, ll);
        const long long idx = ((long long)b * CC + o) * CC + h * 64 + e;
        Wch[idx] = hh;
        Wcl[idx] = ll;
    }
}

// ---------------- launch ----------------
extern "C" void kernel_launch(void* const* d_in, const int* in_sizes, int n_in,
                              void* d_out, int out_size)
{
    (void)in_sizes; (void)n_in; (void)out_size;
    const float* x      = (const float*)d_in[0];
    const float* y      = (const float*)d_in[1];
    const float* kv_w   = (const float*)d_in[2];
    const float* q_w    = (const float*)d_in[3];
    const float* proj_w = (const float*)d_in[4];
    const float* proj_b = (const float*)d_in[5];
    const float* temp   = (const float*)d_in[6];
    float* out = (float*)d_out;

    __nv_bfloat16 *xh, *xl, *yh, *yl, *wh, *wl, *qwh, *qwl, *kvh, *kvl, *qh, *ql, *Wch, *Wcl;
    float *nkp, *nqp, *Sp, *ap;
    cudaGetSymbolAddress((void**)&xh,  g_xh);  cudaGetSymbolAddress((void**)&xl,  g_xl);
    cudaGetSymbolAddress((void**)&yh,  g_yh);  cudaGetSymbolAddress((void**)&yl,  g_yl);
    cudaGetSymbolAddress((void**)&wh,  g_wh);  cudaGetSymbolAddress((void**)&wl,  g_wl);
    cudaGetSymbolAddress((void**)&qwh, g_qwh); cudaGetSymbolAddress((void**)&qwl, g_qwl);
    cudaGetSymbolAddress((void**)&kvh, g_kvh); cudaGetSymbolAddress((void**)&kvl, g_kvl);
    cudaGetSymbolAddress((void**)&qh,  g_qh);  cudaGetSymbolAddress((void**)&ql,  g_ql);
    cudaGetSymbolAddress((void**)&Wch, g_Wch); cudaGetSymbolAddress((void**)&Wcl, g_Wcl);
    cudaGetSymbolAddress((void**)&nkp, g_nk_part);
    cudaGetSymbolAddress((void**)&nqp, g_nq_part);
    cudaGetSymbolAddress((void**)&Sp,  g_Spart);
    cudaGetSymbolAddress((void**)&ap,  g_attn);

    cudaFuncSetAttribute(gemm_wm, cudaFuncAttributeMaxDynamicSharedMemorySize, SMEM_DYN);

    // 0) split fp32 inputs into hi/lo bf16 planes
    conv_kernel<<<16384, 256>>>((const float4*)x,    (uint2*)xh,  (uint2*)xl,  4194304);
    conv_kernel<<< 8192, 256>>>((const float4*)y,    (uint2*)yh,  (uint2*)yl,  2097152);
    conv_kernel<<<  512, 256>>>((const float4*)kv_w, (uint2*)wh,  (uint2*)wl,   131072);
    conv_kernel<<<  128, 256>>>((const float4*)q_w,  (uint2*)qwh, (uint2*)qwl,   32768);

    // 1) kv = x @ kv_w^T  (M=32768, N=1024, K=512) -> planes
    gemm_wm<<<dim3(8, 256, 1), 256, SMEM_DYN>>>(
        xh, xl, 512, 0, wh, wl, 512, 0,
        kvh, kvl, nullptr, 1024, 0, nullptr, 512, 0);

    // 2) q = y @ q_w^T    (M=32768, N=512, K=256) -> planes
    gemm_wm<<<dim3(4, 256, 1), 256, SMEM_DYN>>>(
        yh, yl, 256, 0, qwh, qwl, 256, 0,
        qh, ql, nullptr, 512, 0, nullptr, 256, 0);

    // 3) column sum-of-squares
    sumsq_kernel<<<dim3(16, BB), 256>>>(kvh, kvl, qh, ql, nkp, nqp);

    // 4) raw Gram partials
    gram_kernel<<<dim3(8, HH, BB), 256>>>(qh, ql, kvh, kvl, Sp);

    // 5) normalize + temperature + softmax
    attn_kernel<<<dim3(HH, BB), 64>>>(Sp, nqp, nkp, temp, ap);

    // 6) fold attn into projection weights -> Wc planes
    fold_kernel<<<dim3(4, HH, BB), 256>>>(ap, proj_w, Wch, Wcl);

    // 7) out[b] = V_b @ Wc_b^T + proj_b  (M=4096, N=512, K=512, batched) -> fp32
    gemm_wm<<<dim3(4, 32, BB), 256, SMEM_DYN>>>(
        kvh + 512, kvl + 512, 1024, (long long)NN * 1024,
        Wch, Wcl, 512, (long long)CC * CC,
        nullptr, nullptr, out, 512, (long long)NN * CC,
        proj_b, 512, 2);
}

// round 7
// speedup vs baseline: 1.5826x; 1.0978x over previous
#include <cuda_runtime.h>
#include <cuda_bf16.h>
#include <mma.h>
#include <math.h>
#include <stdint.h>

using namespace nvcuda;

#define BB 8
#define NN 4096
#define CC 512
#define HH 8
#define DH 64
#define EPSF 1e-12f

// smem tile geometry: 128 rows x 32 bf16, padded to 40 elems (80B) per row
#define SPITCH 40
#define PLANE  5120          // 128*40 bf16 elems per plane
#define STAGE_E 20480        // 4 planes (Ahi, Alo, Bhi, Blo)
#define NST 3
#define SMEM_DYN 122880      // 3 stages * 20480 elems * 2B (>= epilogue 128*132*4)

// ---------------- scratch (device globals; no allocs) ----------------
__device__ __nv_bfloat16 g_xh [16777216], g_xl [16777216];   // x planes   [B*N,512]
__device__ __nv_bfloat16 g_yh [ 8388608], g_yl [ 8388608];   // y planes   [B*N,256]
__device__ __nv_bfloat16 g_wh [  262144], g_wl [  262144];   // kv_w k-rows [512,512]
__device__ __nv_bfloat16 g_qwh[  131072], g_qwl[  131072];   // q_w        [512,256]
__device__ __nv_bfloat16 g_pwh[  262144], g_pwl[  262144];   // proj_w     [512,512]
__device__ __nv_bfloat16 g_kh [16777216], g_kl [16777216];   // k planes   [B*N,512]
__device__ __nv_bfloat16 g_qh [16777216], g_ql [16777216];   // q planes   [B*N,512]
__device__ __nv_bfloat16 g_Tth[ 2097152], g_Ttl[ 2097152];   // Tt planes  [B,512,512]
__device__ __nv_bfloat16 g_M2h[ 2097152], g_M2l[ 2097152];   // M2 planes  [B,512,512]
__device__ float g_nk_part[16 * BB * CC];
__device__ float g_nq_part[16 * BB * CC];
__device__ float g_Spart[8 * BB * HH * DH * DH];
__device__ float g_attn [BB * HH * DH * DH];

// ---------------- helpers ----------------
__device__ __forceinline__ uint32_t smem_u32(const void* p) {
    uint32_t a;
    asm("{ .reg .u64 t; cvta.to.shared.u64 t, %1; cvt.u32.u64 %0, t; }" : "=r"(a) : "l"(p));
    return a;
}
__device__ __forceinline__ void split2(float v, __nv_bfloat16& h, __nv_bfloat16& l) {
    h = __float2bfloat16(v);
    l = __float2bfloat16(v - __bfloat162float(h));
}
__device__ __forceinline__ uint32_t pack2(__nv_bfloat16 a, __nv_bfloat16 b) {
    return (uint32_t)__bfloat16_as_ushort(a) | ((uint32_t)__bfloat16_as_ushort(b) << 16);
}
__device__ __forceinline__ float bsum(__nv_bfloat16 h, __nv_bfloat16 l) {
    return __bfloat162float(h) + __bfloat162float(l);
}
#define CPA16(s, g)  asm volatile("cp.async.cg.shared.global [%0], [%1], 16;" :: "r"(s), "l"(g))
#define CPA_COMMIT() asm volatile("cp.async.commit_group;")
#define CPA_WAIT1()  asm volatile("cp.async.wait_group 1;")
#define CPA_WAIT0()  asm volatile("cp.async.wait_group 0;")

// ---------------- conversion: fp32 -> hi/lo bf16 planes ----------------
__global__ void conv_kernel(const float4* __restrict__ in,
                            uint2* __restrict__ oh, uint2* __restrict__ ol, int n4) {
    int i = blockIdx.x * 256 + threadIdx.x;
    if (i < n4) {
        float4 v = in[i];
        __nv_bfloat16 h0, h1, h2, h3, l0, l1, l2, l3;
        split2(v.x, h0, l0); split2(v.y, h1, l1);
        split2(v.z, h2, l2); split2(v.w, h3, l3);
        oh[i] = make_uint2(pack2(h0, h1), pack2(h2, h3));
        ol[i] = make_uint2(pack2(l0, l1), pack2(l2, l3));
    }
}

// ---------------- wmma split GEMM ----------------
// C[m,n] = sum_k A[m,k]*B[n,k], A = Ah+Al, B = Bh+Bl (bf16 planes).
// Accumulates Ah*Bh + Ah*Bl + Al*Bh in fp32 (Markidis split).
// mode 0: write hi/lo bf16 planes Ch, Cl. mode 2: write f32 Cf + bias.
__global__ __launch_bounds__(256, 1)
void gemm_wm(const __nv_bfloat16* __restrict__ Ah, const __nv_bfloat16* __restrict__ Al,
             int pA, long long sA,
             const __nv_bfloat16* __restrict__ Bh, const __nv_bfloat16* __restrict__ Bl,
             int pB, long long sB,
             __nv_bfloat16* __restrict__ Ch, __nv_bfloat16* __restrict__ Cl,
             float* __restrict__ Cf, int pC, long long sC,
             const float* __restrict__ bias, int K, int mode)
{
    extern __shared__ char smraw[];
    __nv_bfloat16* sbf = (__nv_bfloat16*)smraw;
    float* sf = (float*)smraw;
    const int t = threadIdx.x;
    const int wid = t >> 5;
    const int bz = blockIdx.z;
    Ah += (long long)bz * sA; Al += (long long)bz * sA;
    Bh += (long long)bz * sB; Bl += (long long)bz * sB;
    const int m0 = blockIdx.y * 128, n0 = blockIdx.x * 128;
    const int wm = (wid & 1) * 64, wn = (wid >> 1) * 32;   // warp tile 64x32

    const int prow = t >> 2;        // 0..63
    const int pch  = (t & 3) * 8;   // k-elem offset (8 elems = 16B)

    const __nv_bfloat16* gp[4] = { Ah + (long long)m0 * pA, Al + (long long)m0 * pA,
                                   Bh + (long long)n0 * pB, Bl + (long long)n0 * pB };
    const int pp[4] = { pA, pA, pB, pB };

    const int nkb = K >> 5;

    auto produce = [&](int s, int kb) {
        const uint32_t sb = smem_u32(sbf + s * STAGE_E);
        #pragma unroll
        for (int pl = 0; pl < 4; ++pl) {
            #pragma unroll
            for (int hf = 0; hf < 2; ++hf) {
                const int row = hf * 64 + prow;
                const __nv_bfloat16* g = gp[pl] + (long long)row * pp[pl] + kb + pch;
                const uint32_t sa = sb + (uint32_t)(pl * PLANE + row * SPITCH + pch) * 2u;
                CPA16(sa, g);
            }
        }
        CPA_COMMIT();
    };

    produce(0, 0);
    produce(1, 32);

    wmma::fragment<wmma::accumulator, 16, 16, 16, float> acc[4][2];
    #pragma unroll
    for (int i = 0; i < 4; ++i)
        #pragma unroll
        for (int j = 0; j < 2; ++j) wmma::fill_fragment(acc[i][j], 0.0f);

    for (int i = 0; i < nkb; ++i) {
        if (i + 1 < nkb) { CPA_WAIT1(); } else { CPA_WAIT0(); }
        __syncthreads();
        const int s = i % NST;
        const __nv_bfloat16* sa_h = sbf + s * STAGE_E;
        const __nv_bfloat16* sa_l = sa_h + PLANE;
        const __nv_bfloat16* sb_h = sa_h + 2 * PLANE;
        const __nv_bfloat16* sb_l = sa_h + 3 * PLANE;
        #pragma unroll
        for (int kk = 0; kk < 32; kk += 16) {
            wmma::fragment<wmma::matrix_a, 16, 16, 16, __nv_bfloat16, wmma::row_major> fah[4], fal[4];
            wmma::fragment<wmma::matrix_b, 16, 16, 16, __nv_bfloat16, wmma::col_major> fbh[2], fbl[2];
            #pragma unroll
            for (int im = 0; im < 4; ++im) {
                wmma::load_matrix_sync(fah[im], sa_h + (wm + im * 16) * SPITCH + kk, SPITCH);
                wmma::load_matrix_sync(fal[im], sa_l + (wm + im * 16) * SPITCH + kk, SPITCH);
            }
            #pragma unroll
            for (int in_ = 0; in_ < 2; ++in_) {
                wmma::load_matrix_sync(fbh[in_], sb_h + (wn + in_ * 16) * SPITCH + kk, SPITCH);
                wmma::load_matrix_sync(fbl[in_], sb_l + (wn + in_ * 16) * SPITCH + kk, SPITCH);
            }
            #pragma unroll
            for (int im = 0; im < 4; ++im)
                #pragma unroll
                for (int in_ = 0; in_ < 2; ++in_) {
                    wmma::mma_sync(acc[im][in_], fah[im], fbh[in_], acc[im][in_]);
                    wmma::mma_sync(acc[im][in_], fah[im], fbl[in_], acc[im][in_]);
                    wmma::mma_sync(acc[im][in_], fal[im], fbh[in_], acc[im][in_]);
                }
        }
        __syncthreads();
        if (i + 2 < nkb) produce((i + 2) % NST, (i + 2) * 32);
    }

    // ---- epilogue: stage fp32 tile in smem (pitch 132, reuses pipeline smem) ----
    __syncthreads();
    #pragma unroll
    for (int im = 0; im < 4; ++im)
        #pragma unroll
        for (int in_ = 0; in_ < 2; ++in_)
            wmma::store_matrix_sync(sf + (wm + im * 16) * 132 + wn + in_ * 16,
                                    acc[im][in_], 132, wmma::mem_row_major);
    __syncthreads();

    const int row = t >> 1, half = (t & 1) * 64;
    const float* sr = sf + row * 132 + half;
    if (mode == 0) {
        __nv_bfloat16* dh = Ch + (long long)bz * sC + (long long)(m0 + row) * pC + n0 + half;
        __nv_bfloat16* dl = Cl + (long long)bz * sC + (long long)(m0 + row) * pC + n0 + half;
        #pragma unroll
        for (int j = 0; j < 8; ++j) {
            uint4 hv, lv;
            uint32_t* hp = (uint32_t*)&hv;
            uint32_t* lp = (uint32_t*)&lv;
            #pragma unroll
            for (int e = 0; e < 4; ++e) {
                __nv_bfloat16 h0, h1, l0, l1;
                split2(sr[j * 8 + e * 2 + 0], h0, l0);
                split2(sr[j * 8 + e * 2 + 1], h1, l1);
                hp[e] = pack2(h0, h1);
                lp[e] = pack2(l0, l1);
            }
            *(uint4*)(dh + j * 8) = hv;
            *(uint4*)(dl + j * 8) = lv;
        }
    } else {
        float* dst = Cf + (long long)bz * sC + (long long)(m0 + row) * pC + n0 + half;
        const float* bp = bias + n0 + half;
        #pragma unroll
        for (int j = 0; j < 16; ++j) {
            float4 v = make_float4(sr[j * 4 + 0] + bp[j * 4 + 0],
                                   sr[j * 4 + 1] + bp[j * 4 + 1],
                                   sr[j * 4 + 2] + bp[j * 4 + 2],
                                   sr[j * 4 + 3] + bp[j * 4 + 3]);
            *(float4*)(dst + j * 4) = v;
        }
    }
}

// ---------------- sumsq over k and q planes (both pitch 512) ----------------
__global__ __launch_bounds__(256) void sumsq_kernel(
    const __nv_bfloat16* __restrict__ kh, const __nv_bfloat16* __restrict__ kl,
    const __nv_bfloat16* __restrict__ qh,  const __nv_bfloat16* __restrict__ ql,
    float* __restrict__ nk_part, float* __restrict__ nq_part)
{
    const int chunk = blockIdx.x, b = blockIdx.y, t = threadIdx.x;
    const int n0 = chunk * 256;
    const long long base = ((long long)b * NN + n0) * 512;
    float ak0 = 0.f, ak1 = 0.f, aq0 = 0.f, aq1 = 0.f;
    for (int n = 0; n < 256; ++n) {
        const long long o = base + (long long)n * 512;
        float v0 = bsum(kh[o + t],       kl[o + t]);
        float v1 = bsum(kh[o + t + 256], kl[o + t + 256]);
        float w0 = bsum(qh[o + t],       ql[o + t]);
        float w1 = bsum(qh[o + t + 256], ql[o + t + 256]);
        ak0 += v0 * v0; ak1 += v1 * v1; aq0 += w0 * w0; aq1 += w1 * w1;
    }
    nk_part[(chunk * BB + b) * CC + t]       = ak0;
    nk_part[(chunk * BB + b) * CC + t + 256] = ak1;
    nq_part[(chunk * BB + b) * CC + t]       = aq0;
    nq_part[(chunk * BB + b) * CC + t + 256] = aq1;
}

// ---------------- gram (q,k planes, pitch 512) ----------------
__global__ __launch_bounds__(256) void gram_kernel(
    const __nv_bfloat16* __restrict__ qh, const __nv_bfloat16* __restrict__ ql,
    const __nv_bfloat16* __restrict__ kh, const __nv_bfloat16* __restrict__ kl,
    float* __restrict__ Spart)
{
    const int ns = blockIdx.x, h = blockIdx.y, b = blockIdx.z;
    const int n0 = ns * (NN / 8);
    __shared__ float qs[16][64];
    __shared__ float ks[16][64];
    const int t = threadIdx.x;
    const int lr = t >> 4;
    const int lc = (t & 15) * 4;
    const int tx = t & 15, ty = t >> 4;
    const long long base = ((long long)b * NN) * 512 + h * 64;

    float acc[4][4];
    #pragma unroll
    for (int i = 0; i < 4; ++i)
        #pragma unroll
        for (int j = 0; j < 4; ++j) acc[i][j] = 0.0f;

    for (int nt = 0; nt < NN / 8; nt += 16) {
        const int n = n0 + nt;
        const long long o = base + (long long)(n + lr) * 512 + lc;
        float2 qa0 = __bfloat1622float2(*(const __nv_bfloat162*)(qh + o));
        float2 qa1 = __bfloat1622float2(*(const __nv_bfloat162*)(qh + o + 2));
        float2 qb0 = __bfloat1622float2(*(const __nv_bfloat162*)(ql + o));
        float2 qb1 = __bfloat1622float2(*(const __nv_bfloat162*)(ql + o + 2));
        float2 ka0 = __bfloat1622float2(*(const __nv_bfloat162*)(kh + o));
        float2 ka1 = __bfloat1622float2(*(const __nv_bfloat162*)(kh + o + 2));
        float2 kb0 = __bfloat1622float2(*(const __nv_bfloat162*)(kl + o));
        float2 kb1 = __bfloat1622float2(*(const __nv_bfloat162*)(kl + o + 2));
        __syncthreads();
        qs[lr][lc + 0] = qa0.x + qb0.x; qs[lr][lc + 1] = qa0.y + qb0.y;
        qs[lr][lc + 2] = qa1.x + qb1.x; qs[lr][lc + 3] = qa1.y + qb1.y;
        ks[lr][lc + 0] = ka0.x + kb0.x; ks[lr][lc + 1] = ka0.y + kb0.y;
        ks[lr][lc + 2] = ka1.x + kb1.x; ks[lr][lc + 3] = ka1.y + kb1.y;
        __syncthreads();
        #pragma unroll
        for (int kk = 0; kk < 16; ++kk) {
            float a[4], c[4];
            *(float4*)a = *(float4*)&qs[kk][ty * 4];
            *(float4*)c = *(float4*)&ks[kk][tx * 4];
            #pragma unroll
            for (int i = 0; i < 4; ++i)
                #pragma unroll
                for (int j = 0; j < 4; ++j)
                    acc[i][j] += a[i] * c[j];
        }
    }
    float* dst = Spart + ((((long long)ns * BB + b) * HH + h) * DH) * DH;
    #pragma unroll
    for (int i = 0; i < 4; ++i)
        #pragma unroll
        for (int j = 0; j < 4; ++j)
            dst[(ty * 4 + i) * 64 + tx * 4 + j] = acc[i][j];
}

// ---------------- attn: reduce + normalize + softmax ----------------
__global__ void attn_kernel(
    const float* __restrict__ Spart,
    const float* __restrict__ nq_part, const float* __restrict__ nk_part,
    const float* __restrict__ temp, float* __restrict__ attn)
{
    const int h = blockIdx.x, b = blockIdx.y, d = threadIdx.x;
    __shared__ float snk[64];
    const int c = h * 64 + d;
    float sk = 0.f, sq = 0.f;
    #pragma unroll
    for (int ch = 0; ch < 16; ++ch) {
        sk += nk_part[(ch * BB + b) * CC + c];
        sq += nq_part[(ch * BB + b) * CC + c];
    }
    snk[d] = fmaxf(sqrtf(sk), EPSF);
    const float nqv = fmaxf(sqrtf(sq), EPSF);
    __syncthreads();
    const float tv = temp[h];
    float vals[64];
    float mx = -1e30f;
    #pragma unroll
    for (int e = 0; e < 64; ++e) {
        float s = 0.f;
        #pragma unroll
        for (int ns = 0; ns < 8; ++ns)
            s += Spart[((((long long)ns * BB + b) * HH + h) * DH + d) * DH + e];
        float v = s * tv / (nqv * snk[e]);
        vals[e] = v;
        mx = fmaxf(mx, v);
    }
    float sum = 0.f;
    #pragma unroll
    for (int e = 0; e < 64; ++e) { vals[e] = expf(vals[e] - mx); sum += vals[e]; }
    const float inv = 1.0f / sum;
    float* row = attn + (((long long)(b * HH + h) * DH) * DH) + (long long)d * DH;
    #pragma unroll
    for (int e = 0; e < 64; ++e) row[e] = vals[e] * inv;
}

// ---------------- Tt[b,c,h*64+d] = sum_e attn[b,h,d,e]*kv_w[512+h*64+e, c] ----
__global__ __launch_bounds__(256) void tkern(
    const float* __restrict__ attn, const float* __restrict__ kv_w,
    __nv_bfloat16* __restrict__ Tth, __nv_bfloat16* __restrict__ Ttl)
{
    const int b = blockIdx.x, h = blockIdx.y;
    __shared__ float AT[64][65];   // AT[d][e]
    const float* Ab = attn + (((long long)(b * HH + h) * DH) * DH);
    for (int i = threadIdx.x; i < 4096; i += 256) AT[i >> 6][i & 63] = Ab[i];
    __syncthreads();
    const float* Wv = kv_w + (long long)(512 + h * 64) * CC;   // [e, c]
    for (int half = 0; half < 2; ++half) {
        const int c = half * 256 + threadIdx.x;
        float acc[64];
        #pragma unroll
        for (int d = 0; d < 64; ++d) acc[d] = 0.f;
        for (int e = 0; e < 64; ++e) {
            const float wv = Wv[(long long)e * CC + c];
            #pragma unroll
            for (int d = 0; d < 64; ++d) acc[d] += AT[d][e] * wv;
        }
        const long long base = ((long long)b * CC + c) * CC + h * 64;
        #pragma unroll
        for (int d = 0; d < 64; d += 2) {
            __nv_bfloat16 h0, l0, h1, l1;
            split2(acc[d],     h0, l0);
            split2(acc[d + 1], h1, l1);
            *(uint32_t*)(Tth + base + d) = pack2(h0, h1);
            *(uint32_t*)(Ttl + base + d) = pack2(l0, l1);
        }
    }
}

// ---------------- launch ----------------
extern "C" void kernel_launch(void* const* d_in, const int* in_sizes, int n_in,
                              void* d_out, int out_size)
{
    (void)in_sizes; (void)n_in; (void)out_size;
    const float* x      = (const float*)d_in[0];
    const float* y      = (const float*)d_in[1];
    const float* kv_w   = (const float*)d_in[2];
    const float* q_w    = (const float*)d_in[3];
    const float* proj_w = (const float*)d_in[4];
    const float* proj_b = (const float*)d_in[5];
    const float* temp   = (const float*)d_in[6];
    float* out = (float*)d_out;

    __nv_bfloat16 *xh, *xl, *yh, *yl, *wh, *wl, *qwh, *qwl, *pwh, *pwl;
    __nv_bfloat16 *kh, *kl, *qh, *ql, *Tth, *Ttl, *M2h, *M2l;
    float *nkp, *nqp, *Sp, *ap;
    cudaGetSymbolAddress((void**)&xh,  g_xh);  cudaGetSymbolAddress((void**)&xl,  g_xl);
    cudaGetSymbolAddress((void**)&yh,  g_yh);  cudaGetSymbolAddress((void**)&yl,  g_yl);
    cudaGetSymbolAddress((void**)&wh,  g_wh);  cudaGetSymbolAddress((void**)&wl,  g_wl);
    cudaGetSymbolAddress((void**)&qwh, g_qwh); cudaGetSymbolAddress((void**)&qwl, g_qwl);
    cudaGetSymbolAddress((void**)&pwh, g_pwh); cudaGetSymbolAddress((void**)&pwl, g_pwl);
    cudaGetSymbolAddress((void**)&kh,  g_kh);  cudaGetSymbolAddress((void**)&kl,  g_kl);
    cudaGetSymbolAddress((void**)&qh,  g_qh);  cudaGetSymbolAddress((void**)&ql,  g_ql);
    cudaGetSymbolAddress((void**)&Tth, g_Tth); cudaGetSymbolAddress((void**)&Ttl, g_Ttl);
    cudaGetSymbolAddress((void**)&M2h, g_M2h); cudaGetSymbolAddress((void**)&M2l, g_M2l);
    cudaGetSymbolAddress((void**)&nkp, g_nk_part);
    cudaGetSymbolAddress((void**)&nqp, g_nq_part);
    cudaGetSymbolAddress((void**)&Sp,  g_Spart);
    cudaGetSymbolAddress((void**)&ap,  g_attn);

    cudaFuncSetAttribute(gemm_wm, cudaFuncAttributeMaxDynamicSharedMemorySize, SMEM_DYN);

    // 0) split fp32 inputs into hi/lo bf16 planes
    conv_kernel<<<16384, 256>>>((const float4*)x,      (uint2*)xh,  (uint2*)xl,  4194304);
    conv_kernel<<< 8192, 256>>>((const float4*)y,      (uint2*)yh,  (uint2*)yl,  2097152);
    conv_kernel<<<  256, 256>>>((const float4*)kv_w,   (uint2*)wh,  (uint2*)wl,    65536); // k rows only
    conv_kernel<<<  128, 256>>>((const float4*)q_w,    (uint2*)qwh, (uint2*)qwl,   32768);
    conv_kernel<<<  256, 256>>>((const float4*)proj_w, (uint2*)pwh, (uint2*)pwl,   65536);

    // 1) k = x @ Wk^T  (M=32768, N=512, K=512) -> planes   [V never computed]
    gemm_wm<<<dim3(4, 256, 1), 256, SMEM_DYN>>>(
        xh, xl, 512, 0, wh, wl, 512, 0,
        kh, kl, nullptr, 512, 0, nullptr, 512, 0);

    // 2) q = y @ q_w^T (M=32768, N=512, K=256) -> planes
    gemm_wm<<<dim3(4, 256, 1), 256, SMEM_DYN>>>(
        yh, yl, 256, 0, qwh, qwl, 256, 0,
        qh, ql, nullptr, 512, 0, nullptr, 256, 0);

    // 3) column sum-of-squares
    sumsq_kernel<<<dim3(16, BB), 256>>>(kh, kl, qh, ql, nkp, nqp);

    // 4) raw Gram partials
    gram_kernel<<<dim3(8, HH, BB), 256>>>(qh, ql, kh, kl, Sp);

    // 5) normalize + temperature + softmax
    attn_kernel<<<dim3(HH, BB), 64>>>(Sp, nqp, nkp, temp, ap);

    // 6a) Tt_b = (blockdiag(attn_b) @ Wv)^T  -> planes
    tkern<<<dim3(BB, HH), 256>>>(ap, kv_w, Tth, Ttl);

    // 6b) M2_b = proj_w @ Tt_b^T  (M=512, N=512, K=512, batched) -> planes
    gemm_wm<<<dim3(4, 4, BB), 256, SMEM_DYN>>>(
        pwh, pwl, 512, 0,
        Tth, Ttl, 512, (long long)CC * CC,
        M2h, M2l, nullptr, 512, (long long)CC * CC, nullptr, 512, 0);

    // 7) out_b = x_b @ M2_b^T + proj_b  (M=4096, N=512, K=512, batched) -> fp32
    gemm_wm<<<dim3(4, 32, BB), 256, SMEM_DYN>>>(
        xh, xl, 512, (long long)NN * 512,
        M2h, M2l, 512, (long long)CC * CC,
        nullptr, nullptr, out, 512, (long long)NN * CC,
        proj_b, 512, 2);
}

// round 8
// speedup vs baseline: 1.7564x; 1.1098x over previous
#include <cuda_runtime.h>
#include <cuda_bf16.h>
#include <mma.h>
#include <math.h>
#include <stdint.h>

using namespace nvcuda;

#define BB 8
#define NN 4096
#define CC 512
#define HH 8
#define DH 64
#define EPSF 1e-12f

// smem tile geometry: 128 rows x 32 bf16, padded to 40 elems (80B) per row
#define SPITCH 40
#define PLANE  5120          // 128*40 bf16 elems per plane
#define STAGE_E 20480        // 4 planes (Ahi, Alo, Bhi, Blo)
#define SMEM_DYN 81920       // 2 stages * 20480 elems * 2B (>= epilogue 128*132*4 = 67584)

// ---------------- scratch (device globals; no allocs) ----------------
__device__ __nv_bfloat16 g_xh [16777216], g_xl [16777216];   // x planes   [B*N,512]
__device__ __nv_bfloat16 g_yh [ 8388608], g_yl [ 8388608];   // y planes   [B*N,256]
__device__ __nv_bfloat16 g_wh [  262144], g_wl [  262144];   // kv_w k-rows [512,512]
__device__ __nv_bfloat16 g_qwh[  131072], g_qwl[  131072];   // q_w        [512,256]
__device__ __nv_bfloat16 g_pwh[  262144], g_pwl[  262144];   // proj_w     [512,512]
__device__ __nv_bfloat16 g_kh [16777216], g_kl [16777216];   // k planes   [B*N,512]
__device__ __nv_bfloat16 g_qh [16777216], g_ql [16777216];   // q planes   [B*N,512]
__device__ __nv_bfloat16 g_Tth[ 2097152], g_Ttl[ 2097152];   // Tt planes  [B,512,512]
__device__ __nv_bfloat16 g_M2h[ 2097152], g_M2l[ 2097152];   // M2 planes  [B,512,512]
__device__ float g_nk_part[16 * BB * CC];
__device__ float g_nq_part[16 * BB * CC];
__device__ float g_Spart[8 * BB * HH * DH * DH];
__device__ float g_attn [BB * HH * DH * DH];

// ---------------- helpers ----------------
__device__ __forceinline__ uint32_t smem_u32(const void* p) {
    uint32_t a;
    asm("{ .reg .u64 t; cvta.to.shared.u64 t, %1; cvt.u32.u64 %0, t; }" : "=r"(a) : "l"(p));
    return a;
}
__device__ __forceinline__ void split2(float v, __nv_bfloat16& h, __nv_bfloat16& l) {
    h = __float2bfloat16(v);
    l = __float2bfloat16(v - __bfloat162float(h));
}
__device__ __forceinline__ uint32_t pack2(__nv_bfloat16 a, __nv_bfloat16 b) {
    return (uint32_t)__bfloat16_as_ushort(a) | ((uint32_t)__bfloat16_as_ushort(b) << 16);
}
__device__ __forceinline__ float bsum(__nv_bfloat16 h, __nv_bfloat16 l) {
    return __bfloat162float(h) + __bfloat162float(l);
}
#define CPA16(s, g)  asm volatile("cp.async.cg.shared.global [%0], [%1], 16;" :: "r"(s), "l"(g))
#define CPA_COMMIT() asm volatile("cp.async.commit_group;")
#define CPA_WAIT1()  asm volatile("cp.async.wait_group 1;")
#define CPA_WAIT0()  asm volatile("cp.async.wait_group 0;")

// ---------------- conversion: fp32 -> hi/lo bf16 planes ----------------
__global__ void conv_kernel(const float4* __restrict__ in,
                            uint2* __restrict__ oh, uint2* __restrict__ ol, int n4) {
    int i = blockIdx.x * 256 + threadIdx.x;
    if (i < n4) {
        float4 v = in[i];
        __nv_bfloat16 h0, h1, h2, h3, l0, l1, l2, l3;
        split2(v.x, h0, l0); split2(v.y, h1, l1);
        split2(v.z, h2, l2); split2(v.w, h3, l3);
        oh[i] = make_uint2(pack2(h0, h1), pack2(h2, h3));
        ol[i] = make_uint2(pack2(l0, l1), pack2(l2, l3));
    }
}

// ---------------- wmma split GEMM ----------------
// C[m,n] = sum_k A[m,k]*B[n,k], A = Ah+Al, B = Bh+Bl (bf16 planes).
// Accumulates Ah*Bh + Al*Bh + Ah*Bl in fp32, pass-major (no back-to-back RAW).
// 2-stage double buffer, 80KB smem -> 2 CTAs/SM.
// mode 0: write hi/lo bf16 planes Ch, Cl. mode 2: write f32 Cf + bias.
__global__ __launch_bounds__(256, 2)
void gemm_wm(const __nv_bfloat16* __restrict__ Ah, const __nv_bfloat16* __restrict__ Al,
             int pA, long long sA,
             const __nv_bfloat16* __restrict__ Bh, const __nv_bfloat16* __restrict__ Bl,
             int pB, long long sB,
             __nv_bfloat16* __restrict__ Ch, __nv_bfloat16* __restrict__ Cl,
             float* __restrict__ Cf, int pC, long long sC,
             const float* __restrict__ bias, int K, int mode)
{
    extern __shared__ char smraw[];
    __nv_bfloat16* sbf = (__nv_bfloat16*)smraw;
    float* sf = (float*)smraw;
    const int t = threadIdx.x;
    const int wid = t >> 5;
    const int bz = blockIdx.z;
    Ah += (long long)bz * sA; Al += (long long)bz * sA;
    Bh += (long long)bz * sB; Bl += (long long)bz * sB;
    const int m0 = blockIdx.y * 128, n0 = blockIdx.x * 128;
    const int wm = (wid & 1) * 64, wn = (wid >> 1) * 32;   // warp tile 64x32

    const int prow = t >> 2;        // 0..63
    const int pch  = (t & 3) * 8;   // k-elem offset (8 elems = 16B)

    const __nv_bfloat16* gp[4] = { Ah + (long long)m0 * pA, Al + (long long)m0 * pA,
                                   Bh + (long long)n0 * pB, Bl + (long long)n0 * pB };
    const int pp[4] = { pA, pA, pB, pB };

    const int nkb = K >> 5;

    auto produce = [&](int s, int kb) {
        const uint32_t sb = smem_u32(sbf + s * STAGE_E);
        #pragma unroll
        for (int pl = 0; pl < 4; ++pl) {
            #pragma unroll
            for (int hf = 0; hf < 2; ++hf) {
                const int row = hf * 64 + prow;
                const __nv_bfloat16* g = gp[pl] + (long long)row * pp[pl] + kb + pch;
                const uint32_t sa = sb + (uint32_t)(pl * PLANE + row * SPITCH + pch) * 2u;
                CPA16(sa, g);
            }
        }
        CPA_COMMIT();
    };

    produce(0, 0);

    wmma::fragment<wmma::accumulator, 16, 16, 16, float> acc[4][2];
    #pragma unroll
    for (int i = 0; i < 4; ++i)
        #pragma unroll
        for (int j = 0; j < 2; ++j) wmma::fill_fragment(acc[i][j], 0.0f);

    for (int i = 0; i < nkb; ++i) {
        if (i + 1 < nkb) {
            produce((i + 1) & 1, (i + 1) * 32);
            CPA_WAIT1();
        } else {
            CPA_WAIT0();
        }
        __syncthreads();
        const int s = i & 1;
        const __nv_bfloat16* sa_h = sbf + s * STAGE_E;
        const __nv_bfloat16* sa_l = sa_h + PLANE;
        const __nv_bfloat16* sb_h = sa_h + 2 * PLANE;
        const __nv_bfloat16* sb_l = sa_h + 3 * PLANE;
        #pragma unroll
        for (int kk = 0; kk < 32; kk += 16) {
            wmma::fragment<wmma::matrix_a, 16, 16, 16, __nv_bfloat16, wmma::row_major> fah[4], fal[4];
            wmma::fragment<wmma::matrix_b, 16, 16, 16, __nv_bfloat16, wmma::col_major> fbh[2], fbl[2];
            // pass 1: Ah * Bh  (load fah, fbh)
            #pragma unroll
            for (int im = 0; im < 4; ++im)
                wmma::load_matrix_sync(fah[im], sa_h + (wm + im * 16) * SPITCH + kk, SPITCH);
            #pragma unroll
            for (int in_ = 0; in_ < 2; ++in_)
                wmma::load_matrix_sync(fbh[in_], sb_h + (wn + in_ * 16) * SPITCH + kk, SPITCH);
            #pragma unroll
            for (int im = 0; im < 4; ++im)
                #pragma unroll
                for (int in_ = 0; in_ < 2; ++in_)
                    wmma::mma_sync(acc[im][in_], fah[im], fbh[in_], acc[im][in_]);
            // pass 2: Al * Bh  (load fal; fbh still live)
            #pragma unroll
            for (int im = 0; im < 4; ++im)
                wmma::load_matrix_sync(fal[im], sa_l + (wm + im * 16) * SPITCH + kk, SPITCH);
            #pragma unroll
            for (int im = 0; im < 4; ++im)
                #pragma unroll
                for (int in_ = 0; in_ < 2; ++in_)
                    wmma::mma_sync(acc[im][in_], fal[im], fbh[in_], acc[im][in_]);
            // pass 3: Ah * Bl  (load fbl; fah still live)
            #pragma unroll
            for (int in_ = 0; in_ < 2; ++in_)
                wmma::load_matrix_sync(fbl[in_], sb_l + (wn + in_ * 16) * SPITCH + kk, SPITCH);
            #pragma unroll
            for (int im = 0; im < 4; ++im)
                #pragma unroll
                for (int in_ = 0; in_ < 2; ++in_)
                    wmma::mma_sync(acc[im][in_], fah[im], fbl[in_], acc[im][in_]);
        }
        __syncthreads();
    }

    // ---- epilogue: stage fp32 tile in smem (pitch 132, reuses pipeline smem) ----
    #pragma unroll
    for (int im = 0; im < 4; ++im)
        #pragma unroll
        for (int in_ = 0; in_ < 2; ++in_)
            wmma::store_matrix_sync(sf + (wm + im * 16) * 132 + wn + in_ * 16,
                                    acc[im][in_], 132, wmma::mem_row_major);
    __syncthreads();

    const int row = t >> 1, half = (t & 1) * 64;
    const float* sr = sf + row * 132 + half;
    if (mode == 0) {
        __nv_bfloat16* dh = Ch + (long long)bz * sC + (long long)(m0 + row) * pC + n0 + half;
        __nv_bfloat16* dl = Cl + (long long)bz * sC + (long long)(m0 + row) * pC + n0 + half;
        #pragma unroll
        for (int j = 0; j < 8; ++j) {
            uint4 hv, lv;
            uint32_t* hp = (uint32_t*)&hv;
            uint32_t* lp = (uint32_t*)&lv;
            #pragma unroll
            for (int e = 0; e < 4; ++e) {
                __nv_bfloat16 h0, h1, l0, l1;
                split2(sr[j * 8 + e * 2 + 0], h0, l0);
                split2(sr[j * 8 + e * 2 + 1], h1, l1);
                hp[e] = pack2(h0, h1);
                lp[e] = pack2(l0, l1);
            }
            *(uint4*)(dh + j * 8) = hv;
            *(uint4*)(dl + j * 8) = lv;
        }
    } else {
        float* dst = Cf + (long long)bz * sC + (long long)(m0 + row) * pC + n0 + half;
        const float* bp = bias + n0 + half;
        #pragma unroll
        for (int j = 0; j < 16; ++j) {
            float4 v = make_float4(sr[j * 4 + 0] + bp[j * 4 + 0],
                                   sr[j * 4 + 1] + bp[j * 4 + 1],
                                   sr[j * 4 + 2] + bp[j * 4 + 2],
                                   sr[j * 4 + 3] + bp[j * 4 + 3]);
            *(float4*)(dst + j * 4) = v;
        }
    }
}

// ---------------- sumsq over k and q planes (both pitch 512) ----------------
__global__ __launch_bounds__(256) void sumsq_kernel(
    const __nv_bfloat16* __restrict__ kh, const __nv_bfloat16* __restrict__ kl,
    const __nv_bfloat16* __restrict__ qh,  const __nv_bfloat16* __restrict__ ql,
    float* __restrict__ nk_part, float* __restrict__ nq_part)
{
    const int chunk = blockIdx.x, b = blockIdx.y, t = threadIdx.x;
    const int n0 = chunk * 256;
    const long long base = ((long long)b * NN + n0) * 512;
    float ak0 = 0.f, ak1 = 0.f, aq0 = 0.f, aq1 = 0.f;
    for (int n = 0; n < 256; ++n) {
        const long long o = base + (long long)n * 512;
        float v0 = bsum(kh[o + t],       kl[o + t]);
        float v1 = bsum(kh[o + t + 256], kl[o + t + 256]);
        float w0 = bsum(qh[o + t],       ql[o + t]);
        float w1 = bsum(qh[o + t + 256], ql[o + t + 256]);
        ak0 += v0 * v0; ak1 += v1 * v1; aq0 += w0 * w0; aq1 += w1 * w1;
    }
    nk_part[(chunk * BB + b) * CC + t]       = ak0;
    nk_part[(chunk * BB + b) * CC + t + 256] = ak1;
    nq_part[(chunk * BB + b) * CC + t]       = aq0;
    nq_part[(chunk * BB + b) * CC + t + 256] = aq1;
}

// ---------------- gram (q,k planes, pitch 512) ----------------
__global__ __launch_bounds__(256) void gram_kernel(
    const __nv_bfloat16* __restrict__ qh, const __nv_bfloat16* __restrict__ ql,
    const __nv_bfloat16* __restrict__ kh, const __nv_bfloat16* __restrict__ kl,
    float* __restrict__ Spart)
{
    const int ns = blockIdx.x, h = blockIdx.y, b = blockIdx.z;
    const int n0 = ns * (NN / 8);
    __shared__ float qs[16][64];
    __shared__ float ks[16][64];
    const int t = threadIdx.x;
    const int lr = t >> 4;
    const int lc = (t & 15) * 4;
    const int tx = t & 15, ty = t >> 4;
    const long long base = ((long long)b * NN) * 512 + h * 64;

    float acc[4][4];
    #pragma unroll
    for (int i = 0; i < 4; ++i)
        #pragma unroll
        for (int j = 0; j < 4; ++j) acc[i][j] = 0.0f;

    for (int nt = 0; nt < NN / 8; nt += 16) {
        const int n = n0 + nt;
        const long long o = base + (long long)(n + lr) * 512 + lc;
        float2 qa0 = __bfloat1622float2(*(const __nv_bfloat162*)(qh + o));
        float2 qa1 = __bfloat1622float2(*(const __nv_bfloat162*)(qh + o + 2));
        float2 qb0 = __bfloat1622float2(*(const __nv_bfloat162*)(ql + o));
        float2 qb1 = __bfloat1622float2(*(const __nv_bfloat162*)(ql + o + 2));
        float2 ka0 = __bfloat1622float2(*(const __nv_bfloat162*)(kh + o));
        float2 ka1 = __bfloat1622float2(*(const __nv_bfloat162*)(kh + o + 2));
        float2 kb0 = __bfloat1622float2(*(const __nv_bfloat162*)(kl + o));
        float2 kb1 = __bfloat1622float2(*(const __nv_bfloat162*)(kl + o + 2));
        __syncthreads();
        qs[lr][lc + 0] = qa0.x + qb0.x; qs[lr][lc + 1] = qa0.y + qb0.y;
        qs[lr][lc + 2] = qa1.x + qb1.x; qs[lr][lc + 3] = qa1.y + qb1.y;
        ks[lr][lc + 0] = ka0.x + kb0.x; ks[lr][lc + 1] = ka0.y + kb0.y;
        ks[lr][lc + 2] = ka1.x + kb1.x; ks[lr][lc + 3] = ka1.y + kb1.y;
        __syncthreads();
        #pragma unroll
        for (int kk = 0; kk < 16; ++kk) {
            float a[4], c[4];
            *(float4*)a = *(float4*)&qs[kk][ty * 4];
            *(float4*)c = *(float4*)&ks[kk][tx * 4];
            #pragma unroll
            for (int i = 0; i < 4; ++i)
                #pragma unroll
                for (int j = 0; j < 4; ++j)
                    acc[i][j] += a[i] * c[j];
        }
    }
    float* dst = Spart + ((((long long)ns * BB + b) * HH + h) * DH) * DH;
    #pragma unroll
    for (int i = 0; i < 4; ++i)
        #pragma unroll
        for (int j = 0; j < 4; ++j)
            dst[(ty * 4 + i) * 64 + tx * 4 + j] = acc[i][j];
}

// ---------------- attn: reduce + normalize + softmax ----------------
__global__ void attn_kernel(
    const float* __restrict__ Spart,
    const float* __restrict__ nq_part, const float* __restrict__ nk_part,
    const float* __restrict__ temp, float* __restrict__ attn)
{
    const int h = blockIdx.x, b = blockIdx.y, d = threadIdx.x;
    __shared__ float snk[64];
    const int c = h * 64 + d;
    float sk = 0.f, sq = 0.f;
    #pragma unroll
    for (int ch = 0; ch < 16; ++ch) {
        sk += nk_part[(ch * BB + b) * CC + c];
        sq += nq_part[(ch * BB + b) * CC + c];
    }
    snk[d] = fmaxf(sqrtf(sk), EPSF);
    const float nqv = fmaxf(sqrtf(sq), EPSF);
    __syncthreads();
    const float tv = temp[h];
    float vals[64];
    float mx = -1e30f;
    #pragma unroll
    for (int e = 0; e < 64; ++e) {
        float s = 0.f;
        #pragma unroll
        for (int ns = 0; ns < 8; ++ns)
            s += Spart[((((long long)ns * BB + b) * HH + h) * DH + d) * DH + e];
        float v = s * tv / (nqv * snk[e]);
        vals[e] = v;
        mx = fmaxf(mx, v);
    }
    float sum = 0.f;
    #pragma unroll
    for (int e = 0; e < 64; ++e) { vals[e] = expf(vals[e] - mx); sum += vals[e]; }
    const float inv = 1.0f / sum;
    float* row = attn + (((long long)(b * HH + h) * DH) * DH) + (long long)d * DH;
    #pragma unroll
    for (int e = 0; e < 64; ++e) row[e] = vals[e] * inv;
}

// ---------------- Tt[b,c,h*64+d] = sum_e attn[b,h,d,e]*kv_w[512+h*64+e, c] ----
__global__ __launch_bounds__(256) void tkern(
    const float* __restrict__ attn, const float* __restrict__ kv_w,
    __nv_bfloat16* __restrict__ Tth, __nv_bfloat16* __restrict__ Ttl)
{
    const int b = blockIdx.x, h = blockIdx.y;
    __shared__ float AT[64][65];   // AT[d][e]
    const float* Ab = attn + (((long long)(b * HH + h) * DH) * DH);
    for (int i = threadIdx.x; i < 4096; i += 256) AT[i >> 6][i & 63] = Ab[i];
    __syncthreads();
    const float* Wv = kv_w + (long long)(512 + h * 64) * CC;   // [e, c]
    for (int half = 0; half < 2; ++half) {
        const int c = half * 256 + threadIdx.x;
        float acc[64];
        #pragma unroll
        for (int d = 0; d < 64; ++d) acc[d] = 0.f;
        for (int e = 0; e < 64; ++e) {
            const float wv = Wv[(long long)e * CC + c];
            #pragma unroll
            for (int d = 0; d < 64; ++d) acc[d] += AT[d][e] * wv;
        }
        const long long base = ((long long)b * CC + c) * CC + h * 64;
        #pragma unroll
        for (int d = 0; d < 64; d += 2) {
            __nv_bfloat16 h0, l0, h1, l1;
            split2(acc[d],     h0, l0);
            split2(acc[d + 1], h1, l1);
            *(uint32_t*)(Tth + base + d) = pack2(h0, h1);
            *(uint32_t*)(Ttl + base + d) = pack2(l0, l1);
        }
    }
}

// ---------------- launch ----------------
extern "C" void kernel_launch(void* const* d_in, const int* in_sizes, int n_in,
                              void* d_out, int out_size)
{
    (void)in_sizes; (void)n_in; (void)out_size;
    const float* x      = (const float*)d_in[0];
    const float* y      = (const float*)d_in[1];
    const float* kv_w   = (const float*)d_in[2];
    const float* q_w    = (const float*)d_in[3];
    const float* proj_w = (const float*)d_in[4];
    const float* proj_b = (const float*)d_in[5];
    const float* temp   = (const float*)d_in[6];
    float* out = (float*)d_out;

    __nv_bfloat16 *xh, *xl, *yh, *yl, *wh, *wl, *qwh, *qwl, *pwh, *pwl;
    __nv_bfloat16 *kh, *kl, *qh, *ql, *Tth, *Ttl, *M2h, *M2l;
    float *nkp, *nqp, *Sp, *ap;
    cudaGetSymbolAddress((void**)&xh,  g_xh);  cudaGetSymbolAddress((void**)&xl,  g_xl);
    cudaGetSymbolAddress((void**)&yh,  g_yh);  cudaGetSymbolAddress((void**)&yl,  g_yl);
    cudaGetSymbolAddress((void**)&wh,  g_wh);  cudaGetSymbolAddress((void**)&wl,  g_wl);
    cudaGetSymbolAddress((void**)&qwh, g_qwh); cudaGetSymbolAddress((void**)&qwl, g_qwl);
    cudaGetSymbolAddress((void**)&pwh, g_pwh); cudaGetSymbolAddress((void**)&pwl, g_pwl);
    cudaGetSymbolAddress((void**)&kh,  g_kh);  cudaGetSymbolAddress((void**)&kl,  g_kl);
    cudaGetSymbolAddress((void**)&qh,  g_qh);  cudaGetSymbolAddress((void**)&ql,  g_ql);
    cudaGetSymbolAddress((void**)&Tth, g_Tth); cudaGetSymbolAddress((void**)&Ttl, g_Ttl);
    cudaGetSymbolAddress((void**)&M2h, g_M2h); cudaGetSymbolAddress((void**)&M2l, g_M2l);
    cudaGetSymbolAddress((void**)&nkp, g_nk_part);
    cudaGetSymbolAddress((void**)&nqp, g_nq_part);
    cudaGetSymbolAddress((void**)&Sp,  g_Spart);
    cudaGetSymbolAddress((void**)&ap,  g_attn);

    cudaFuncSetAttribute(gemm_wm, cudaFuncAttributeMaxDynamicSharedMemorySize, SMEM_DYN);

    // 0) split fp32 inputs into hi/lo bf16 planes
    conv_kernel<<<16384, 256>>>((const float4*)x,      (uint2*)xh,  (uint2*)xl,  4194304);
    conv_kernel<<< 8192, 256>>>((const float4*)y,      (uint2*)yh,  (uint2*)yl,  2097152);
    conv_kernel<<<  256, 256>>>((const float4*)kv_w,   (uint2*)wh,  (uint2*)wl,    65536); // k rows only
    conv_kernel<<<  128, 256>>>((const float4*)q_w,    (uint2*)qwh, (uint2*)qwl,   32768);
    conv_kernel<<<  256, 256>>>((const float4*)proj_w, (uint2*)pwh, (uint2*)pwl,   65536);

    // 1) k = x @ Wk^T  (M=32768, N=512, K=512) -> planes   [V never computed]
    gemm_wm<<<dim3(4, 256, 1), 256, SMEM_DYN>>>(
        xh, xl, 512, 0, wh, wl, 512, 0,
        kh, kl, nullptr, 512, 0, nullptr, 512, 0);

    // 2) q = y @ q_w^T (M=32768, N=512, K=256) -> planes
    gemm_wm<<<dim3(4, 256, 1), 256, SMEM_DYN>>>(
        yh, yl, 256, 0, qwh, qwl, 256, 0,
        qh, ql, nullptr, 512, 0, nullptr, 256, 0);

    // 3) column sum-of-squares
    sumsq_kernel<<<dim3(16, BB), 256>>>(kh, kl, qh, ql, nkp, nqp);

    // 4) raw Gram partials
    gram_kernel<<<dim3(8, HH, BB), 256>>>(qh, ql, kh, kl, Sp);

    // 5) normalize + temperature + softmax
    attn_kernel<<<dim3(HH, BB), 64>>>(Sp, nqp, nkp, temp, ap);

    // 6a) Tt_b = (blockdiag(attn_b) @ Wv)^T  -> planes
    tkern<<<dim3(BB, HH), 256>>>(ap, kv_w, Tth, Ttl);

    // 6b) M2_b = proj_w @ Tt_b^T  (M=512, N=512, K=512, batched) -> planes
    gemm_wm<<<dim3(4, 4, BB), 256, SMEM_DYN>>>(
        pwh, pwl, 512, 0,
        Tth, Ttl, 512, (long long)CC * CC,
        M2h, M2l, nullptr, 512, (long long)CC * CC, nullptr, 512, 0);

    // 7) out_b = x_b @ M2_b^T + proj_b  (M=4096, N=512, K=512, batched) -> fp32
    gemm_wm<<<dim3(4, 32, BB), 256, SMEM_DYN>>>(
        xh, xl, 512, (long long)NN * 512,
        M2h, M2l, 512, (long long)CC * CC,
        nullptr, nullptr, out, 512, (long long)NN * CC,
        proj_b, 512, 2);
}

// round 9
// speedup vs baseline: 2.6913x; 1.5323x over previous
#include <cuda_runtime.h>
#include <cuda_fp16.h>
#include <mma.h>
#include <math.h>
#include <stdint.h>

using namespace nvcuda;

#define BB 8
#define NN 4096
#define CC 512
#define HH 8
#define DH 64
#define EPSF 1e-12f

// smem tile geometry: 128 rows x 32 fp16, padded to 40 elems (80B) per row
#define SPITCH 40
#define PLANE  5120          // 128*40 fp16 elems per plane
#define STAGE_E 15360        // 3 planes (A, Bhi, Blo)
#define SMEM_DYN 69632       // >= max(2*15360*2 = 61440, epilogue 128*132*4 = 67584)

// ---------------- scratch (device globals; no allocs) ----------------
__device__ __half g_x16[16777216];    // x fp16      [B*N,512]
__device__ __half g_y16[ 8388608];    // y fp16      [B*N,256]
__device__ __half g_wh [  262144], g_wl [  262144];  // kv_w k-rows hi/lo [512,512]
__device__ __half g_qwh[  131072], g_qwl[  131072];  // q_w hi/lo   [512,256]
__device__ __half g_p16[  262144];    // proj_w fp16 [512,512]
__device__ __half g_Tth[ 2097152], g_Ttl[ 2097152];  // Tt hi/lo    [B,512,512]
__device__ __half g_M2h[ 2097152], g_M2l[ 2097152];  // M2 hi/lo    [B,512,512]
__device__ float g_k [16777216];      // k fp32      [B*N,512]
__device__ float g_q [16777216];      // q fp32      [B*N,512]
__device__ float g_nk_part[8 * BB * CC];
__device__ float g_nq_part[8 * BB * CC];
__device__ float g_Spart[8 * BB * HH * DH * DH];
__device__ float g_attn [BB * HH * DH * DH];

// ---------------- helpers ----------------
__device__ __forceinline__ uint32_t smem_u32(const void* p) {
    uint32_t a;
    asm("{ .reg .u64 t; cvta.to.shared.u64 t, %1; cvt.u32.u64 %0, t; }" : "=r"(a) : "l"(p));
    return a;
}
__device__ __forceinline__ void split2h(float v, __half& h, __half& l) {
    h = __float2half_rn(v);
    l = __float2half_rn(v - __half2float(h));
}
__device__ __forceinline__ uint32_t pack2h(__half a, __half b) {
    return (uint32_t)__half_as_ushort(a) | ((uint32_t)__half_as_ushort(b) << 16);
}
#define CPA16(s, g)  asm volatile("cp.async.cg.shared.global [%0], [%1], 16;" :: "r"(s), "l"(g))
#define CPA_COMMIT() asm volatile("cp.async.commit_group;")
#define CPA_WAIT1()  asm volatile("cp.async.wait_group 1;")
#define CPA_WAIT0()  asm volatile("cp.async.wait_group 0;")

// ---------------- conversions ----------------
__global__ void convh_kernel(const float4* __restrict__ in, uint2* __restrict__ o16, int n4) {
    int i = blockIdx.x * 256 + threadIdx.x;
    if (i < n4) {
        float4 v = in[i];
        o16[i] = make_uint2(pack2h(__float2half_rn(v.x), __float2half_rn(v.y)),
                            pack2h(__float2half_rn(v.z), __float2half_rn(v.w)));
    }
}
__global__ void convhl_kernel(const float4* __restrict__ in,
                              uint2* __restrict__ oh, uint2* __restrict__ ol, int n4) {
    int i = blockIdx.x * 256 + threadIdx.x;
    if (i < n4) {
        float4 v = in[i];
        __half h0, h1, h2, h3, l0, l1, l2, l3;
        split2h(v.x, h0, l0); split2h(v.y, h1, l1);
        split2h(v.z, h2, l2); split2h(v.w, h3, l3);
        oh[i] = make_uint2(pack2h(h0, h1), pack2h(h2, h3));
        ol[i] = make_uint2(pack2h(l0, l1), pack2h(l2, l3));
    }
}

// ---------------- fp16 2-pass split GEMM ----------------
// C[m,n] = sum_k A[m,k]*B[n,k], A single fp16 plane, B = Bh+Bl fp16 planes.
// acc += A*Bh ; acc += A*Bl  (error ~ A_lost*B ~ 2^-12 relative).
// mode 0: write hi/lo fp16 planes Ch, Cl. mode 1: fp32 Cf. mode 2: fp32 Cf + bias.
__global__ __launch_bounds__(256, 2)
void gemm_wm(const __half* __restrict__ A, int pA, long long sA,
             const __half* __restrict__ Bh, const __half* __restrict__ Bl,
             int pB, long long sB,
             __half* __restrict__ Ch, __half* __restrict__ Cl,
             float* __restrict__ Cf, int pC, long long sC,
             const float* __restrict__ bias, int K, int mode)
{
    extern __shared__ char smraw[];
    __half* sbf = (__half*)smraw;
    float* sf = (float*)smraw;
    const int t = threadIdx.x;
    const int wid = t >> 5;
    const int bz = blockIdx.z;
    A  += (long long)bz * sA;
    Bh += (long long)bz * sB;
    Bl += (long long)bz * sB;
    const int m0 = blockIdx.y * 128, n0 = blockIdx.x * 128;
    const int wm = (wid & 1) * 64, wn = (wid >> 1) * 32;   // warp tile 64x32

    const int prow = t >> 2;        // 0..63
    const int pch  = (t & 3) * 8;   // k-elem offset (8 elems = 16B)

    const __half* gp[3] = { A + (long long)m0 * pA, Bh + (long long)n0 * pB, Bl + (long long)n0 * pB };
    const int pp[3] = { pA, pB, pB };

    const int nkb = K >> 5;

    auto produce = [&](int s, int kb) {
        const uint32_t sb = smem_u32(sbf + s * STAGE_E);
        #pragma unroll
        for (int pl = 0; pl < 3; ++pl) {
            #pragma unroll
            for (int hf = 0; hf < 2; ++hf) {
                const int row = hf * 64 + prow;
                const __half* g = gp[pl] + (long long)row * pp[pl] + kb + pch;
                const uint32_t sa = sb + (uint32_t)(pl * PLANE + row * SPITCH + pch) * 2u;
                CPA16(sa, g);
            }
        }
        CPA_COMMIT();
    };

    produce(0, 0);

    wmma::fragment<wmma::accumulator, 16, 16, 16, float> acc[4][2];
    #pragma unroll
    for (int i = 0; i < 4; ++i)
        #pragma unroll
        for (int j = 0; j < 2; ++j) wmma::fill_fragment(acc[i][j], 0.0f);

    for (int i = 0; i < nkb; ++i) {
        if (i + 1 < nkb) {
            produce((i + 1) & 1, (i + 1) * 32);
            CPA_WAIT1();
        } else {
            CPA_WAIT0();
        }
        __syncthreads();
        const int s = i & 1;
        const __half* sa  = sbf + s * STAGE_E;
        const __half* sbh = sa + PLANE;
        const __half* sbl = sa + 2 * PLANE;
        #pragma unroll
        for (int kk = 0; kk < 32; kk += 16) {
            wmma::fragment<wmma::matrix_a, 16, 16, 16, __half, wmma::row_major> fa[4];
            wmma::fragment<wmma::matrix_b, 16, 16, 16, __half, wmma::col_major> fbh[2], fbl[2];
            #pragma unroll
            for (int im = 0; im < 4; ++im)
                wmma::load_matrix_sync(fa[im], sa + (wm + im * 16) * SPITCH + kk, SPITCH);
            #pragma unroll
            for (int in_ = 0; in_ < 2; ++in_)
                wmma::load_matrix_sync(fbh[in_], sbh + (wn + in_ * 16) * SPITCH + kk, SPITCH);
            #pragma unroll
            for (int im = 0; im < 4; ++im)
                #pragma unroll
                for (int in_ = 0; in_ < 2; ++in_)
                    wmma::mma_sync(acc[im][in_], fa[im], fbh[in_], acc[im][in_]);
            #pragma unroll
            for (int in_ = 0; in_ < 2; ++in_)
                wmma::load_matrix_sync(fbl[in_], sbl + (wn + in_ * 16) * SPITCH + kk, SPITCH);
            #pragma unroll
            for (int im = 0; im < 4; ++im)
                #pragma unroll
                for (int in_ = 0; in_ < 2; ++in_)
                    wmma::mma_sync(acc[im][in_], fa[im], fbl[in_], acc[im][in_]);
        }
        __syncthreads();
    }

    // ---- epilogue: stage fp32 tile in smem (pitch 132), then coalesced out ----
    #pragma unroll
    for (int im = 0; im < 4; ++im)
        #pragma unroll
        for (int in_ = 0; in_ < 2; ++in_)
            wmma::store_matrix_sync(sf + (wm + im * 16) * 132 + wn + in_ * 16,
                                    acc[im][in_], 132, wmma::mem_row_major);
    __syncthreads();

    const int row = t >> 1, half = (t & 1) * 64;
    const float* sr = sf + row * 132 + half;
    if (mode == 0) {
        __half* dh = Ch + (long long)bz * sC + (long long)(m0 + row) * pC + n0 + half;
        __half* dl = Cl + (long long)bz * sC + (long long)(m0 + row) * pC + n0 + half;
        #pragma unroll
        for (int j = 0; j < 8; ++j) {
            uint4 hv, lv;
            uint32_t* hp = (uint32_t*)&hv;
            uint32_t* lp = (uint32_t*)&lv;
            #pragma unroll
            for (int e = 0; e < 4; ++e) {
                __half h0, h1, l0, l1;
                split2h(sr[j * 8 + e * 2 + 0], h0, l0);
                split2h(sr[j * 8 + e * 2 + 1], h1, l1);
                hp[e] = pack2h(h0, h1);
                lp[e] = pack2h(l0, l1);
            }
            *(uint4*)(dh + j * 8) = hv;
            *(uint4*)(dl + j * 8) = lv;
        }
    } else {
        float* dst = Cf + (long long)bz * sC + (long long)(m0 + row) * pC + n0 + half;
        #pragma unroll
        for (int j = 0; j < 16; ++j) {
            float4 v = make_float4(sr[j * 4 + 0], sr[j * 4 + 1], sr[j * 4 + 2], sr[j * 4 + 3]);
            if (mode == 2) {
                const float* bp = bias + n0 + half + j * 4;
                v.x += bp[0]; v.y += bp[1]; v.z += bp[2]; v.w += bp[3];
            }
            *(float4*)(dst + j * 4) = v;
        }
    }
}

// ---------------- gram + fused column sumsq (fp32 q,k inputs) ----------------
__global__ __launch_bounds__(256) void gram_kernel(
    const float* __restrict__ q, const float* __restrict__ k,
    float* __restrict__ Spart, float* __restrict__ nq_part, float* __restrict__ nk_part)
{
    const int ns = blockIdx.x, h = blockIdx.y, b = blockIdx.z;
    const int n0 = ns * (NN / 8);
    __shared__ float qs[16][64];
    __shared__ float ks[16][64];
    __shared__ float redq[4][64];
    __shared__ float redk[4][64];
    const int t = threadIdx.x;
    const int lr = t >> 4;
    const int lc = (t & 15) * 4;
    const int tx = t & 15, ty = t >> 4;
    const int col = t & 63, quarter = t >> 6;
    const long long base = ((long long)b * NN) * 512 + h * 64;

    float acc[4][4];
    #pragma unroll
    for (int i = 0; i < 4; ++i)
        #pragma unroll
        for (int j = 0; j < 4; ++j) acc[i][j] = 0.0f;
    float sq_q = 0.f, sq_k = 0.f;

    for (int nt = 0; nt < NN / 8; nt += 16) {
        const int n = n0 + nt;
        const long long o = base + (long long)(n + lr) * 512 + lc;
        float4 qv = *(const float4*)(q + o);
        float4 kv = *(const float4*)(k + o);
        __syncthreads();
        *(float4*)&qs[lr][lc] = qv;
        *(float4*)&ks[lr][lc] = kv;
        __syncthreads();
        #pragma unroll
        for (int kk = 0; kk < 16; ++kk) {
            float a[4], c[4];
            *(float4*)a = *(float4*)&qs[kk][ty * 4];
            *(float4*)c = *(float4*)&ks[kk][tx * 4];
            #pragma unroll
            for (int i = 0; i < 4; ++i)
                #pragma unroll
                for (int j = 0; j < 4; ++j)
                    acc[i][j] += a[i] * c[j];
        }
        #pragma unroll
        for (int r = 0; r < 4; ++r) {
            float vq = qs[quarter * 4 + r][col];
            float vk = ks[quarter * 4 + r][col];
            sq_q += vq * vq;
            sq_k += vk * vk;
        }
    }
    float* dst = Spart + ((((long long)ns * BB + b) * HH + h) * DH) * DH;
    #pragma unroll
    for (int i = 0; i < 4; ++i)
        #pragma unroll
        for (int j = 0; j < 4; ++j)
            dst[(ty * 4 + i) * 64 + tx * 4 + j] = acc[i][j];

    redq[quarter][col] = sq_q;
    redk[quarter][col] = sq_k;
    __syncthreads();
    if (t < 64) {
        float s = redq[0][t] + redq[1][t] + redq[2][t] + redq[3][t];
        nq_part[(ns * BB + b) * CC + h * 64 + t] = s;
    } else if (t < 128) {
        const int c = t - 64;
        float s = redk[0][c] + redk[1][c] + redk[2][c] + redk[3][c];
        nk_part[(ns * BB + b) * CC + h * 64 + c] = s;
    }
}

// ---------------- attn: reduce + normalize + softmax ----------------
__global__ void attn_kernel(
    const float* __restrict__ Spart,
    const float* __restrict__ nq_part, const float* __restrict__ nk_part,
    const float* __restrict__ temp, float* __restrict__ attn)
{
    const int h = blockIdx.x, b = blockIdx.y, d = threadIdx.x;
    __shared__ float snk[64];
    const int c = h * 64 + d;
    float sk = 0.f, sq = 0.f;
    #pragma unroll
    for (int ch = 0; ch < 8; ++ch) {
        sk += nk_part[(ch * BB + b) * CC + c];
        sq += nq_part[(ch * BB + b) * CC + c];
    }
    snk[d] = fmaxf(sqrtf(sk), EPSF);
    const float nqv = fmaxf(sqrtf(sq), EPSF);
    __syncthreads();
    const float tv = temp[h];
    float vals[64];
    float mx = -1e30f;
    #pragma unroll
    for (int e = 0; e < 64; ++e) {
        float s = 0.f;
        #pragma unroll
        for (int ns = 0; ns < 8; ++ns)
            s += Spart[((((long long)ns * BB + b) * HH + h) * DH + d) * DH + e];
        float v = s * tv / (nqv * snk[e]);
        vals[e] = v;
        mx = fmaxf(mx, v);
    }
    float sum = 0.f;
    #pragma unroll
    for (int e = 0; e < 64; ++e) { vals[e] = expf(vals[e] - mx); sum += vals[e]; }
    const float inv = 1.0f / sum;
    float* row = attn + (((long long)(b * HH + h) * DH) * DH) + (long long)d * DH;
    #pragma unroll
    for (int e = 0; e < 64; ++e) row[e] = vals[e] * inv;
}

// ---------------- Tt[b,c,h*64+d] = sum_e attn[b,h,d,e]*kv_w[512+h*64+e, c] ----
__global__ __launch_bounds__(256) void tkern(
    const float* __restrict__ attn, const float* __restrict__ kv_w,
    __half* __restrict__ Tth, __half* __restrict__ Ttl)
{
    const int b = blockIdx.x, h = blockIdx.y;
    __shared__ float AT[64][65];   // AT[d][e]
    const float* Ab = attn + (((long long)(b * HH + h) * DH) * DH);
    for (int i = threadIdx.x; i < 4096; i += 256) AT[i >> 6][i & 63] = Ab[i];
    __syncthreads();
    const float* Wv = kv_w + (long long)(512 + h * 64) * CC;   // [e, c]
    for (int half_ = 0; half_ < 2; ++half_) {
        const int c = half_ * 256 + threadIdx.x;
        float acc[64];
        #pragma unroll
        for (int d = 0; d < 64; ++d) acc[d] = 0.f;
        for (int e = 0; e < 64; ++e) {
            const float wv = Wv[(long long)e * CC + c];
            #pragma unroll
            for (int d = 0; d < 64; ++d) acc[d] += AT[d][e] * wv;
        }
        const long long base = ((long long)b * CC + c) * CC + h * 64;
        #pragma unroll
        for (int d = 0; d < 64; d += 2) {
            __half h0, l0, h1, l1;
            split2h(acc[d],     h0, l0);
            split2h(acc[d + 1], h1, l1);
            *(uint32_t*)(Tth + base + d) = pack2h(h0, h1);
            *(uint32_t*)(Ttl + base + d) = pack2h(l0, l1);
        }
    }
}

// ---------------- launch ----------------
extern "C" void kernel_launch(void* const* d_in, const int* in_sizes, int n_in,
                              void* d_out, int out_size)
{
    (void)in_sizes; (void)n_in; (void)out_size;
    const float* x      = (const float*)d_in[0];
    const float* y      = (const float*)d_in[1];
    const float* kv_w   = (const float*)d_in[2];
    const float* q_w    = (const float*)d_in[3];
    const float* proj_w = (const float*)d_in[4];
    const float* proj_b = (const float*)d_in[5];
    const float* temp   = (const float*)d_in[6];
    float* out = (float*)d_out;

    __half *x16, *y16, *wh, *wl, *qwh, *qwl, *p16, *Tth, *Ttl, *M2h, *M2l;
    float *kp, *qp, *nkp, *nqp, *Sp, *ap;
    cudaGetSymbolAddress((void**)&x16, g_x16);
    cudaGetSymbolAddress((void**)&y16, g_y16);
    cudaGetSymbolAddress((void**)&wh,  g_wh);  cudaGetSymbolAddress((void**)&wl,  g_wl);
    cudaGetSymbolAddress((void**)&qwh, g_qwh); cudaGetSymbolAddress((void**)&qwl, g_qwl);
    cudaGetSymbolAddress((void**)&p16, g_p16);
    cudaGetSymbolAddress((void**)&Tth, g_Tth); cudaGetSymbolAddress((void**)&Ttl, g_Ttl);
    cudaGetSymbolAddress((void**)&M2h, g_M2h); cudaGetSymbolAddress((void**)&M2l, g_M2l);
    cudaGetSymbolAddress((void**)&kp,  g_k);
    cudaGetSymbolAddress((void**)&qp,  g_q);
    cudaGetSymbolAddress((void**)&nkp, g_nk_part);
    cudaGetSymbolAddress((void**)&nqp, g_nq_part);
    cudaGetSymbolAddress((void**)&Sp,  g_Spart);
    cudaGetSymbolAddress((void**)&ap,  g_attn);

    cudaFuncSetAttribute(gemm_wm, cudaFuncAttributeMaxDynamicSharedMemorySize, SMEM_DYN);

    // 0) conversions
    convh_kernel<<<16384, 256>>>((const float4*)x,      (uint2*)x16, 4194304);
    convh_kernel<<< 8192, 256>>>((const float4*)y,      (uint2*)y16, 2097152);
    convh_kernel<<<  256, 256>>>((const float4*)proj_w, (uint2*)p16,   65536);
    convhl_kernel<<< 256, 256>>>((const float4*)kv_w,   (uint2*)wh,  (uint2*)wl,  65536); // k rows only
    convhl_kernel<<< 128, 256>>>((const float4*)q_w,    (uint2*)qwh, (uint2*)qwl, 32768);

    // 1) k = x @ Wk^T  (M=32768, N=512, K=512) -> fp32
    gemm_wm<<<dim3(4, 256, 1), 256, SMEM_DYN>>>(
        x16, 512, 0, wh, wl, 512, 0,
        nullptr, nullptr, kp, 512, 0, nullptr, 512, 1);

    // 2) q = y @ q_w^T (M=32768, N=512, K=256) -> fp32
    gemm_wm<<<dim3(4, 256, 1), 256, SMEM_DYN>>>(
        y16, 256, 0, qwh, qwl, 256, 0,
        nullptr, nullptr, qp, 512, 0, nullptr, 256, 1);

    // 3) Gram partials + fused column sumsq
    gram_kernel<<<dim3(8, HH, BB), 256>>>(qp, kp, Sp, nqp, nkp);

    // 4) normalize + temperature + softmax
    attn_kernel<<<dim3(HH, BB), 64>>>(Sp, nqp, nkp, temp, ap);

    // 5) Tt_b = (blockdiag(attn_b) @ Wv)^T  -> fp16 hi/lo planes
    tkern<<<dim3(BB, HH), 256>>>(ap, kv_w, Tth, Ttl);

    // 6) M2_b = proj_w @ Tt_b^T  (M=512, N=512, K=512, batched) -> fp16 hi/lo
    gemm_wm<<<dim3(4, 4, BB), 256, SMEM_DYN>>>(
        p16, 512, 0,
        Tth, Ttl, 512, (long long)CC * CC,
        M2h, M2l, nullptr, 512, (long long)CC * CC, nullptr, 512, 0);

    // 7) out_b = x_b @ M2_b^T + proj_b  (M=4096, N=512, K=512, batched) -> fp32
    gemm_wm<<<dim3(4, 32, BB), 256, SMEM_DYN>>>(
        x16, 512, (long long)NN * 512,
        M2h, M2l, 512, (long long)CC * CC,
        nullptr, nullptr, out, 512, (long long)NN * CC,
        proj_b, 512, 2);
}

// round 10
// speedup vs baseline: 3.1155x; 1.1576x over previous
#include <cuda_runtime.h>
#include <cuda_fp16.h>
#include <mma.h>
#include <math.h>
#include <stdint.h>

using namespace nvcuda;

#define BB 8
#define NN 4096
#define CC 512
#define HH 8
#define DH 64
#define EPSF 1e-12f
#define GNS 4                // gram n-splits

// gemm smem tile: 128 rows x 32 fp16, padded to 40 elems (80B) per row
#define SPITCH 40
#define PLANE  5120
#define STAGE_E 15360        // 3 planes (A, Bhi, Blo)
#define SMEM_DYN 69632       // >= max(2*15360*2, epilogue 128*132*4)

// ---------------- scratch (device globals; no allocs) ----------------
__device__ __half g_x16[16777216];    // x fp16      [B*N,512]
__device__ __half g_y16[ 8388608];    // y fp16      [B*N,256]
__device__ __half g_wh [  262144], g_wl [  262144];  // kv_w k-rows hi/lo [512,512]
__device__ __half g_qwh[  131072], g_qwl[  131072];  // q_w hi/lo   [512,256]
__device__ __half g_p16[  262144];    // proj_w fp16 [512,512]
__device__ __half g_k16[16777216];    // k fp16      [B*N,512]
__device__ __half g_q16[16777216];    // q fp16      [B*N,512]
__device__ __half g_Tth[ 2097152], g_Ttl[ 2097152];  // Tt hi/lo    [B,512,512]
__device__ __half g_M2h[ 2097152], g_M2l[ 2097152];  // M2 hi/lo    [B,512,512]
__device__ float g_nk_part[GNS * BB * CC];
__device__ float g_nq_part[GNS * BB * CC];
__device__ float g_Spart[GNS * BB * HH * DH * DH];
__device__ float g_attn [BB * HH * DH * DH];

// ---------------- helpers ----------------
__device__ __forceinline__ uint32_t smem_u32(const void* p) {
    uint32_t a;
    asm("{ .reg .u64 t; cvta.to.shared.u64 t, %1; cvt.u32.u64 %0, t; }" : "=r"(a) : "l"(p));
    return a;
}
__device__ __forceinline__ void split2h(float v, __half& h, __half& l) {
    h = __float2half_rn(v);
    l = __float2half_rn(v - __half2float(h));
}
__device__ __forceinline__ uint32_t pack2h(__half a, __half b) {
    return (uint32_t)__half_as_ushort(a) | ((uint32_t)__half_as_ushort(b) << 16);
}
#define CPA16(s, g)  asm volatile("cp.async.cg.shared.global [%0], [%1], 16;" :: "r"(s), "l"(g))
#define CPA_COMMIT() asm volatile("cp.async.commit_group;")
#define CPA_WAIT1()  asm volatile("cp.async.wait_group 1;")
#define CPA_WAIT0()  asm volatile("cp.async.wait_group 0;")

// ---------------- conversions ----------------
__global__ void convh_kernel(const float4* __restrict__ in, uint2* __restrict__ o16, int n4) {
    int i = blockIdx.x * 256 + threadIdx.x;
    if (i < n4) {
        float4 v = in[i];
        o16[i] = make_uint2(pack2h(__float2half_rn(v.x), __float2half_rn(v.y)),
                            pack2h(__float2half_rn(v.z), __float2half_rn(v.w)));
    }
}
__global__ void convhl_kernel(const float4* __restrict__ in,
                              uint2* __restrict__ oh, uint2* __restrict__ ol, int n4) {
    int i = blockIdx.x * 256 + threadIdx.x;
    if (i < n4) {
        float4 v = in[i];
        __half h0, h1, h2, h3, l0, l1, l2, l3;
        split2h(v.x, h0, l0); split2h(v.y, h1, l1);
        split2h(v.z, h2, l2); split2h(v.w, h3, l3);
        oh[i] = make_uint2(pack2h(h0, h1), pack2h(h2, h3));
        ol[i] = make_uint2(pack2h(l0, l1), pack2h(l2, l3));
    }
}

// ---------------- fp16 2-pass split GEMM ----------------
// C[m,n] = sum_k A[m,k]*B[n,k], A single fp16 plane, B = Bh+Bl fp16 planes.
// mode 0: hi/lo fp16 planes. mode 2: fp32 + bias. mode 3: single fp16 plane.
__global__ __launch_bounds__(256, 2)
void gemm_wm(const __half* __restrict__ A, int pA, long long sA,
             const __half* __restrict__ Bh, const __half* __restrict__ Bl,
             int pB, long long sB,
             __half* __restrict__ Ch, __half* __restrict__ Cl,
             float* __restrict__ Cf, int pC, long long sC,
             const float* __restrict__ bias, int K, int mode)
{
    extern __shared__ char smraw[];
    __half* sbf = (__half*)smraw;
    float* sf = (float*)smraw;
    const int t = threadIdx.x;
    const int wid = t >> 5;
    const int bz = blockIdx.z;
    A  += (long long)bz * sA;
    Bh += (long long)bz * sB;
    Bl += (long long)bz * sB;
    const int m0 = blockIdx.y * 128, n0 = blockIdx.x * 128;
    const int wm = (wid & 1) * 64, wn = (wid >> 1) * 32;

    const int prow = t >> 2;
    const int pch  = (t & 3) * 8;

    const __half* gp[3] = { A + (long long)m0 * pA, Bh + (long long)n0 * pB, Bl + (long long)n0 * pB };
    const int pp[3] = { pA, pB, pB };

    const int nkb = K >> 5;

    auto produce = [&](int s, int kb) {
        const uint32_t sb = smem_u32(sbf + s * STAGE_E);
        #pragma unroll
        for (int pl = 0; pl < 3; ++pl) {
            #pragma unroll
            for (int hf = 0; hf < 2; ++hf) {
                const int row = hf * 64 + prow;
                const __half* g = gp[pl] + (long long)row * pp[pl] + kb + pch;
                const uint32_t sa = sb + (uint32_t)(pl * PLANE + row * SPITCH + pch) * 2u;
                CPA16(sa, g);
            }
        }
        CPA_COMMIT();
    };

    produce(0, 0);

    wmma::fragment<wmma::accumulator, 16, 16, 16, float> acc[4][2];
    #pragma unroll
    for (int i = 0; i < 4; ++i)
        #pragma unroll
        for (int j = 0; j < 2; ++j) wmma::fill_fragment(acc[i][j], 0.0f);

    for (int i = 0; i < nkb; ++i) {
        if (i + 1 < nkb) {
            produce((i + 1) & 1, (i + 1) * 32);
            CPA_WAIT1();
        } else {
            CPA_WAIT0();
        }
        __syncthreads();
        const int s = i & 1;
        const __half* sa  = sbf + s * STAGE_E;
        const __half* sbh = sa + PLANE;
        const __half* sbl = sa + 2 * PLANE;
        #pragma unroll
        for (int kk = 0; kk < 32; kk += 16) {
            wmma::fragment<wmma::matrix_a, 16, 16, 16, __half, wmma::row_major> fa[4];
            wmma::fragment<wmma::matrix_b, 16, 16, 16, __half, wmma::col_major> fbh[2], fbl[2];
            #pragma unroll
            for (int im = 0; im < 4; ++im)
                wmma::load_matrix_sync(fa[im], sa + (wm + im * 16) * SPITCH + kk, SPITCH);
            #pragma unroll
            for (int in_ = 0; in_ < 2; ++in_)
                wmma::load_matrix_sync(fbh[in_], sbh + (wn + in_ * 16) * SPITCH + kk, SPITCH);
            #pragma unroll
            for (int im = 0; im < 4; ++im)
                #pragma unroll
                for (int in_ = 0; in_ < 2; ++in_)
                    wmma::mma_sync(acc[im][in_], fa[im], fbh[in_], acc[im][in_]);
            #pragma unroll
            for (int in_ = 0; in_ < 2; ++in_)
                wmma::load_matrix_sync(fbl[in_], sbl + (wn + in_ * 16) * SPITCH + kk, SPITCH);
            #pragma unroll
            for (int im = 0; im < 4; ++im)
                #pragma unroll
                for (int in_ = 0; in_ < 2; ++in_)
                    wmma::mma_sync(acc[im][in_], fa[im], fbl[in_], acc[im][in_]);
        }
        __syncthreads();
    }

    // ---- epilogue via smem (pitch 132) ----
    #pragma unroll
    for (int im = 0; im < 4; ++im)
        #pragma unroll
        for (int in_ = 0; in_ < 2; ++in_)
            wmma::store_matrix_sync(sf + (wm + im * 16) * 132 + wn + in_ * 16,
                                    acc[im][in_], 132, wmma::mem_row_major);
    __syncthreads();

    const int row = t >> 1, half = (t & 1) * 64;
    const float* sr = sf + row * 132 + half;
    if (mode == 0) {
        __half* dh = Ch + (long long)bz * sC + (long long)(m0 + row) * pC + n0 + half;
        __half* dl = Cl + (long long)bz * sC + (long long)(m0 + row) * pC + n0 + half;
        #pragma unroll
        for (int j = 0; j < 8; ++j) {
            uint4 hv, lv;
            uint32_t* hp = (uint32_t*)&hv;
            uint32_t* lp = (uint32_t*)&lv;
            #pragma unroll
            for (int e = 0; e < 4; ++e) {
                __half h0, h1, l0, l1;
                split2h(sr[j * 8 + e * 2 + 0], h0, l0);
                split2h(sr[j * 8 + e * 2 + 1], h1, l1);
                hp[e] = pack2h(h0, h1);
                lp[e] = pack2h(l0, l1);
            }
            *(uint4*)(dh + j * 8) = hv;
            *(uint4*)(dl + j * 8) = lv;
        }
    } else if (mode == 3) {
        __half* dh = Ch + (long long)bz * sC + (long long)(m0 + row) * pC + n0 + half;
        #pragma unroll
        for (int j = 0; j < 8; ++j) {
            uint4 hv;
            uint32_t* hp = (uint32_t*)&hv;
            #pragma unroll
            for (int e = 0; e < 4; ++e)
                hp[e] = pack2h(__float2half_rn(sr[j * 8 + e * 2 + 0]),
                               __float2half_rn(sr[j * 8 + e * 2 + 1]));
            *(uint4*)(dh + j * 8) = hv;
        }
    } else {
        float* dst = Cf + (long long)bz * sC + (long long)(m0 + row) * pC + n0 + half;
        #pragma unroll
        for (int j = 0; j < 16; ++j) {
            float4 v = make_float4(sr[j * 4 + 0], sr[j * 4 + 1], sr[j * 4 + 2], sr[j * 4 + 3]);
            if (mode == 2) {
                const float* bp = bias + n0 + half + j * 4;
                v.x += bp[0]; v.y += bp[1]; v.z += bp[2]; v.w += bp[3];
            }
            *(float4*)(dst + j * 4) = v;
        }
    }
}

// ---------------- tensor-core gram + fused sumsq (fp16 q,k) ----------------
// S[ns,b,h,d,e] = sum_{n in split} q16[b,n,h*64+d] * k16[b,n,h*64+e]
// grid (GNS, H, B), 256 threads (8 warps, 4x2 of 16x32 warp tiles).
__global__ __launch_bounds__(256) void gram_kernel(
    const __half* __restrict__ q16, const __half* __restrict__ k16,
    float* __restrict__ Spart, float* __restrict__ nq_part, float* __restrict__ nk_part)
{
    const int ns = blockIdx.x, h = blockIdx.y, b = blockIdx.z;
    __shared__ __half qs[64 * 72];
    __shared__ __half ks[64 * 72];
    const int t = threadIdx.x;
    const int wid = t >> 5;
    const int wr = wid & 3, wc = wid >> 2;
    const long long base = ((long long)b * NN) * 512 + h * 64;
    const int n0 = ns * (NN / GNS);

    const int lrow  = t >> 3;        // 0..31
    const int lcol8 = (t & 7) * 8;   // col octet base

    wmma::fragment<wmma::accumulator, 16, 16, 16, float> acc[2];
    wmma::fill_fragment(acc[0], 0.0f);
    wmma::fill_fragment(acc[1], 0.0f);
    float sq_q[8], sq_k[8];
    #pragma unroll
    for (int j = 0; j < 8; ++j) { sq_q[j] = 0.f; sq_k[j] = 0.f; }

    for (int ch = 0; ch < (NN / GNS) / 64; ++ch) {
        const int nb = n0 + ch * 64;
        __syncthreads();
        #pragma unroll
        for (int hf = 0; hf < 2; ++hf) {
            const int r = lrow + hf * 32;
            const long long g = base + (long long)(nb + r) * 512 + lcol8;
            uint4 qv = *(const uint4*)(q16 + g);
            uint4 kv = *(const uint4*)(k16 + g);
            *(uint4*)(qs + r * 72 + lcol8) = qv;
            *(uint4*)(ks + r * 72 + lcol8) = kv;
            const __half* qh_ = (const __half*)&qv;
            const __half* kh_ = (const __half*)&kv;
            #pragma unroll
            for (int j = 0; j < 8; ++j) {
                float fq = __half2float(qh_[j]);
                float fk = __half2float(kh_[j]);
                sq_q[j] += fq * fq;
                sq_k[j] += fk * fk;
            }
        }
        __syncthreads();
        #pragma unroll
        for (int nsub = 0; nsub < 4; ++nsub) {
            wmma::fragment<wmma::matrix_a, 16, 16, 16, __half, wmma::col_major> fa;
            wmma::fragment<wmma::matrix_b, 16, 16, 16, __half, wmma::row_major> fb0, fb1;
            wmma::load_matrix_sync(fa,  qs + nsub * 16 * 72 + wr * 16, 72);
            wmma::load_matrix_sync(fb0, ks + nsub * 16 * 72 + wc * 32, 72);
            wmma::load_matrix_sync(fb1, ks + nsub * 16 * 72 + wc * 32 + 16, 72);
            wmma::mma_sync(acc[0], fa, fb0, acc[0]);
            wmma::mma_sync(acc[1], fa, fb1, acc[1]);
        }
    }

    float* dst = Spart + ((((long long)ns * BB + b) * HH + h) * DH) * DH;
    wmma::store_matrix_sync(dst + (wr * 16) * 64 + wc * 32,      acc[0], 64, wmma::mem_row_major);
    wmma::store_matrix_sync(dst + (wr * 16) * 64 + wc * 32 + 16, acc[1], 64, wmma::mem_row_major);

    // deterministic sumsq reduction (reuse qs/ks as fp32 scratch)
    __syncthreads();
    float* redq = (float*)qs;   // 256*8 floats = 8192B <= 9216B
    float* redk = (float*)ks;
    #pragma unroll
    for (int j = 0; j < 8; ++j) { redq[t * 8 + j] = sq_q[j]; redk[t * 8 + j] = sq_k[j]; }
    __syncthreads();
    if (t < 64) {
        const int oct = t >> 3, j = t & 7;
        float sq = 0.f, sk = 0.f;
        #pragma unroll
        for (int m = 0; m < 32; ++m) {
            const int tt = m * 8 + oct;
            sq += redq[tt * 8 + j];
            sk += redk[tt * 8 + j];
        }
        nq_part[(ns * BB + b) * CC + h * 64 + t] = sq;
        nk_part[(ns * BB + b) * CC + h * 64 + t] = sk;
    }
}

// ---------------- attn: reduce + normalize + softmax ----------------
__global__ void attn_kernel(
    const float* __restrict__ Spart,
    const float* __restrict__ nq_part, const float* __restrict__ nk_part,
    const float* __restrict__ temp, float* __restrict__ attn)
{
    const int h = blockIdx.x, b = blockIdx.y, d = threadIdx.x;
    __shared__ float snk[64];
    const int c = h * 64 + d;
    float sk = 0.f, sq = 0.f;
    #pragma unroll
    for (int ch = 0; ch < GNS; ++ch) {
        sk += nk_part[(ch * BB + b) * CC + c];
        sq += nq_part[(ch * BB + b) * CC + c];
    }
    snk[d] = fmaxf(sqrtf(sk), EPSF);
    const float nqv = fmaxf(sqrtf(sq), EPSF);
    __syncthreads();
    const float tv = temp[h];
    float vals[64];
    float mx = -1e30f;
    #pragma unroll
    for (int e = 0; e < 64; ++e) {
        float s = 0.f;
        #pragma unroll
        for (int ns = 0; ns < GNS; ++ns)
            s += Spart[((((long long)ns * BB + b) * HH + h) * DH + d) * DH + e];
        float v = s * tv / (nqv * snk[e]);
        vals[e] = v;
        mx = fmaxf(mx, v);
    }
    float sum = 0.f;
    #pragma unroll
    for (int e = 0; e < 64; ++e) { vals[e] = expf(vals[e] - mx); sum += vals[e]; }
    const float inv = 1.0f / sum;
    float* row = attn + (((long long)(b * HH + h) * DH) * DH) + (long long)d * DH;
    #pragma unroll
    for (int e = 0; e < 64; ++e) row[e] = vals[e] * inv;
}

// ---------------- Tt[b,c,h*64+d] = sum_e attn[b,h,d,e]*kv_w[512+h*64+e, c] ----
__global__ __launch_bounds__(256) void tkern(
    const float* __restrict__ attn, const float* __restrict__ kv_w,
    __half* __restrict__ Tth, __half* __restrict__ Ttl)
{
    const int b = blockIdx.x, h = blockIdx.y;
    __shared__ float AT[64][65];
    const float* Ab = attn + (((long long)(b * HH + h) * DH) * DH);
    for (int i = threadIdx.x; i < 4096; i += 256) AT[i >> 6][i & 63] = Ab[i];
    __syncthreads();
    const float* Wv = kv_w + (long long)(512 + h * 64) * CC;
    for (int half_ = 0; half_ < 2; ++half_) {
        const int c = half_ * 256 + threadIdx.x;
        float acc[64];
        #pragma unroll
        for (int d = 0; d < 64; ++d) acc[d] = 0.f;
        for (int e = 0; e < 64; ++e) {
            const float wv = Wv[(long long)e * CC + c];
            #pragma unroll
            for (int d = 0; d < 64; ++d) acc[d] += AT[d][e] * wv;
        }
        const long long base = ((long long)b * CC + c) * CC + h * 64;
        #pragma unroll
        for (int d = 0; d < 64; d += 2) {
            __half h0, l0, h1, l1;
            split2h(acc[d],     h0, l0);
            split2h(acc[d + 1], h1, l1);
            *(uint32_t*)(Tth + base + d) = pack2h(h0, h1);
            *(uint32_t*)(Ttl + base + d) = pack2h(l0, l1);
        }
    }
}

// ---------------- launch ----------------
extern "C" void kernel_launch(void* const* d_in, const int* in_sizes, int n_in,
                              void* d_out, int out_size)
{
    (void)in_sizes; (void)n_in; (void)out_size;
    const float* x      = (const float*)d_in[0];
    const float* y      = (const float*)d_in[1];
    const float* kv_w   = (const float*)d_in[2];
    const float* q_w    = (const float*)d_in[3];
    const float* proj_w = (const float*)d_in[4];
    const float* proj_b = (const float*)d_in[5];
    const float* temp   = (const float*)d_in[6];
    float* out = (float*)d_out;

    __half *x16, *y16, *wh, *wl, *qwh, *qwl, *p16, *k16, *q16, *Tth, *Ttl, *M2h, *M2l;
    float *nkp, *nqp, *Sp, *ap;
    cudaGetSymbolAddress((void**)&x16, g_x16);
    cudaGetSymbolAddress((void**)&y16, g_y16);
    cudaGetSymbolAddress((void**)&wh,  g_wh);  cudaGetSymbolAddress((void**)&wl,  g_wl);
    cudaGetSymbolAddress((void**)&qwh, g_qwh); cudaGetSymbolAddress((void**)&qwl, g_qwl);
    cudaGetSymbolAddress((void**)&p16, g_p16);
    cudaGetSymbolAddress((void**)&k16, g_k16);
    cudaGetSymbolAddress((void**)&q16, g_q16);
    cudaGetSymbolAddress((void**)&Tth, g_Tth); cudaGetSymbolAddress((void**)&Ttl, g_Ttl);
    cudaGetSymbolAddress((void**)&M2h, g_M2h); cudaGetSymbolAddress((void**)&M2l, g_M2l);
    cudaGetSymbolAddress((void**)&nkp, g_nk_part);
    cudaGetSymbolAddress((void**)&nqp, g_nq_part);
    cudaGetSymbolAddress((void**)&Sp,  g_Spart);
    cudaGetSymbolAddress((void**)&ap,  g_attn);

    cudaFuncSetAttribute(gemm_wm, cudaFuncAttributeMaxDynamicSharedMemorySize, SMEM_DYN);

    // 0) conversions
    convh_kernel<<<16384, 256>>>((const float4*)x,      (uint2*)x16, 4194304);
    convh_kernel<<< 8192, 256>>>((const float4*)y,      (uint2*)y16, 2097152);
    convh_kernel<<<  256, 256>>>((const float4*)proj_w, (uint2*)p16,   65536);
    convhl_kernel<<< 256, 256>>>((const float4*)kv_w,   (uint2*)wh,  (uint2*)wl,  65536);
    convhl_kernel<<< 128, 256>>>((const float4*)q_w,    (uint2*)qwh, (uint2*)qwl, 32768);

    // 1) k = x @ Wk^T  -> fp16 plane
    gemm_wm<<<dim3(4, 256, 1), 256, SMEM_DYN>>>(
        x16, 512, 0, wh, wl, 512, 0,
        k16, nullptr, nullptr, 512, 0, nullptr, 512, 3);

    // 2) q = y @ q_w^T -> fp16 plane
    gemm_wm<<<dim3(4, 256, 1), 256, SMEM_DYN>>>(
        y16, 256, 0, qwh, qwl, 256, 0,
        q16, nullptr, nullptr, 512, 0, nullptr, 256, 3);

    // 3) tensor-core Gram partials + fused sumsq
    gram_kernel<<<dim3(GNS, HH, BB), 256>>>(q16, k16, Sp, nqp, nkp);

    // 4) normalize + temperature + softmax
    attn_kernel<<<dim3(HH, BB), 64>>>(Sp, nqp, nkp, temp, ap);

    // 5) Tt_b = (blockdiag(attn_b) @ Wv)^T -> fp16 hi/lo
    tkern<<<dim3(BB, HH), 256>>>(ap, kv_w, Tth, Ttl);

    // 6) M2_b = proj_w @ Tt_b^T -> fp16 hi/lo
    gemm_wm<<<dim3(4, 4, BB), 256, SMEM_DYN>>>(
        p16, 512, 0,
        Tth, Ttl, 512, (long long)CC * CC,
        M2h, M2l, nullptr, 512, (long long)CC * CC, nullptr, 512, 0);

    // 7) out_b = x_b @ M2_b^T + proj_b -> fp32
    gemm_wm<<<dim3(4, 32, BB), 256, SMEM_DYN>>>(
        x16, 512, (long long)NN * 512,
        M2h, M2l, 512, (long long)CC * CC,
        nullptr, nullptr, out, 512, (long long)NN * CC,
        proj_b, 512, 2);
}